// round 3
// baseline (speedup 1.0000x reference)
#include <cuda_runtime.h>
#include <math.h>

#define SS 2048
#define EE 2048
#define HH 16
#define DNN 128
#define DRR 64
#define RR 512
#define QLRR 1536

// ---------------- scratch (static device globals; no allocations) ----------------
__device__ float g_qa[SS * QLRR];                       // x@w_q_a, rmsnormed in place
__device__ float g_q[SS * HH * (DNN + DRR)];            // 2048 x 3072
__device__ float g_ckv_kpe[SS * (RR + DRR)];            // 2048 x 576
__device__ float g_kfull[SS * (RR + DRR)];              // [ckv_norm | roped k_pe]
__device__ float g_qfull[HH * SS * (RR + DRR)];         // per-head [q_abs | roped q_pe]
__device__ float g_woabs[HH * RR * EE];                 // 16 x 512 x 2048
__device__ float g_scores[(size_t)HH * SS * SS];        // 16 x 2048 x 2048
__device__ float g_octx[SS * HH * RR];                  // [s][h][r] -> 2048 x 8192

// ---------------- generic tiled GEMM: C = A * B (or A * B^T) ----------------
// BM=BN=128, BK=8, 256 threads, 8x8 per thread.
// TRANSB: B is [N,K] k-contiguous (NT gemm).
// CSKIP:  skip blocks fully above the causal diagonal (scores).
// CKLIM:  limit K loop to the causal extent of this M-tile (attn@ckv).
template <bool TRANSB, bool CSKIP, bool CKLIM>
__global__ __launch_bounds__(256) void gemm128(
    const float* __restrict__ A, const float* __restrict__ B, float* __restrict__ C,
    int M, int N, int K, int lda, int ldb, int ldc,
    long long sA, long long sB, long long sC)
{
    int bz = blockIdx.z;
    A += sA * bz; B += sB * bz; C += sC * bz;
    int bx = blockIdx.x, by = blockIdx.y;
    if (CSKIP && bx > by) return;
    int kEnd = CKLIM ? min(K, (by + 1) * 128) : K;

    __shared__ __align__(16) float As[8][128];
    __shared__ __align__(16) float Bs[8][128];

    int tid = threadIdx.x;
    int tx = tid & 15, ty = tid >> 4;
    float acc[8][8];
#pragma unroll
    for (int i = 0; i < 8; i++)
#pragma unroll
        for (int j = 0; j < 8; j++) acc[i][j] = 0.f;

    int aRow = tid >> 1;
    int aCol = (tid & 1) << 2;

    for (int k0 = 0; k0 < kEnd; k0 += 8) {
        // A tile (M always a multiple of 128 in this pipeline; K multiple of 8)
        {
            const float* ap = A + (long long)(by * 128 + aRow) * lda + (k0 + aCol);
            float4 v = *reinterpret_cast<const float4*>(ap);
            As[aCol + 0][aRow] = v.x;
            As[aCol + 1][aRow] = v.y;
            As[aCol + 2][aRow] = v.z;
            As[aCol + 3][aRow] = v.w;
        }
        if (!TRANSB) {
            int bk = tid >> 5;           // 0..7
            int bn = (tid & 31) << 2;    // 0..124
            int gn = bx * 128 + bn;
            const float* bp = B + (long long)(k0 + bk) * ldb + gn;
            float4 v;
            if (gn + 3 < N) {
                v = *reinterpret_cast<const float4*>(bp);
            } else {
                v.x = (gn + 0 < N) ? bp[0] : 0.f;
                v.y = (gn + 1 < N) ? bp[1] : 0.f;
                v.z = (gn + 2 < N) ? bp[2] : 0.f;
                v.w = (gn + 3 < N) ? bp[3] : 0.f;
            }
            *reinterpret_cast<float4*>(&Bs[bk][bn]) = v;
        } else {
            int bn = tid >> 1;           // 0..127
            int bk = (tid & 1) << 2;
            int gn = bx * 128 + bn;
            float4 v = make_float4(0.f, 0.f, 0.f, 0.f);
            if (gn < N)
                v = *reinterpret_cast<const float4*>(B + (long long)gn * ldb + (k0 + bk));
            Bs[bk + 0][bn] = v.x;
            Bs[bk + 1][bn] = v.y;
            Bs[bk + 2][bn] = v.z;
            Bs[bk + 3][bn] = v.w;
        }
        __syncthreads();
#pragma unroll
        for (int kk = 0; kk < 8; kk++) {
            float4 a0 = *reinterpret_cast<const float4*>(&As[kk][ty * 8]);
            float4 a1 = *reinterpret_cast<const float4*>(&As[kk][ty * 8 + 4]);
            float4 b0 = *reinterpret_cast<const float4*>(&Bs[kk][tx * 8]);
            float4 b1 = *reinterpret_cast<const float4*>(&Bs[kk][tx * 8 + 4]);
            float a[8] = {a0.x, a0.y, a0.z, a0.w, a1.x, a1.y, a1.z, a1.w};
            float b[8] = {b0.x, b0.y, b0.z, b0.w, b1.x, b1.y, b1.z, b1.w};
#pragma unroll
            for (int i = 0; i < 8; i++)
#pragma unroll
                for (int j = 0; j < 8; j++)
                    acc[i][j] += a[i] * b[j];
        }
        __syncthreads();
    }

    int mBase = by * 128 + ty * 8, nBase = bx * 128 + tx * 8;
#pragma unroll
    for (int i = 0; i < 8; i++) {
        long long rowoff = (long long)(mBase + i) * ldc;
#pragma unroll
        for (int j = 0; j < 8; j++) {
            int col = nBase + j;
            if (col < N) C[rowoff + col] = acc[i][j];
        }
    }
}

// ---------------- rmsnorm over rows ----------------
__global__ __launch_bounds__(256) void rmsnorm_k(
    const float* __restrict__ in, const float* __restrict__ w, float* __restrict__ out,
    int ncols, int ldin, int ldout)
{
    int row = blockIdx.x;
    const float* ip = in + (long long)row * ldin;
    float* op = out + (long long)row * ldout;
    float ss = 0.f;
    for (int c = threadIdx.x; c < ncols; c += blockDim.x) {
        float v = ip[c];
        ss += v * v;
    }
    __shared__ float sred[32];
#pragma unroll
    for (int o = 16; o > 0; o >>= 1) ss += __shfl_xor_sync(0xffffffffu, ss, o);
    int lane = threadIdx.x & 31, wid = threadIdx.x >> 5;
    if (lane == 0) sred[wid] = ss;
    __syncthreads();
    if (wid == 0) {
        float v = (lane < 8) ? sred[lane] : 0.f;
#pragma unroll
        for (int o = 4; o > 0; o >>= 1) v += __shfl_xor_sync(0xffffffffu, v, o);
        if (lane == 0) sred[0] = v;
    }
    __syncthreads();
    float r = rsqrtf(sred[0] / (float)ncols + 1e-6f);
    for (int c = threadIdx.x; c < ncols; c += blockDim.x) op[c] = ip[c] * r * w[c];
}

// ---------------- RoPE ----------------
__device__ __forceinline__ float2 rope_cs(int pos, int i) {
    float freq = powf(10000.0f, -(float)(2 * i) / 64.0f);
    float ang = (float)pos * freq;
    float c, s;
    sincosf(ang, &s, &c);
    return make_float2(c, s);
}

__global__ void rope_k_kernel(const float* __restrict__ ckv_kpe, float* __restrict__ kfull) {
    int s = blockIdx.x, j = threadIdx.x;  // 64 threads
    const float* src = ckv_kpe + (long long)s * 576 + 512;
    float2 cs = rope_cs(s, j & 31);
    float x = src[j];
    float rot = (j < 32) ? -src[j + 32] : src[j - 32];
    kfull[(long long)s * 576 + 512 + j] = x * cs.x + rot * cs.y;
}

__global__ void rope_q_kernel(const float* __restrict__ q, float* __restrict__ qfull) {
    int s = blockIdx.x, h = blockIdx.y, j = threadIdx.x;  // 64 threads
    const float* src = q + (long long)s * 3072 + h * 192 + 128;
    float2 cs = rope_cs(s, j & 31);
    float x = src[j];
    float rot = (j < 32) ? -src[j + 32] : src[j - 32];
    qfull[((long long)h * SS + s) * 576 + 512 + j] = x * cs.x + rot * cs.y;
}

// ---------------- causal softmax (in place on scores) ----------------
__global__ __launch_bounds__(256) void softmax_causal(float* __restrict__ scores, float scale) {
    int q = blockIdx.x, h = blockIdx.y;
    float* row = scores + ((long long)h * SS + q) * SS;
    int tid = threadIdx.x;
    int n = q + 1;

    float m = -1e30f;
    for (int k = tid; k < n; k += 256) m = fmaxf(m, row[k] * scale);
    __shared__ float sred[32];
#pragma unroll
    for (int o = 16; o > 0; o >>= 1) m = fmaxf(m, __shfl_xor_sync(0xffffffffu, m, o));
    int lane = tid & 31, wid = tid >> 5;
    if (lane == 0) sred[wid] = m;
    __syncthreads();
    if (wid == 0) {
        float v = (lane < 8) ? sred[lane] : -1e30f;
#pragma unroll
        for (int o = 4; o > 0; o >>= 1) v = fmaxf(v, __shfl_xor_sync(0xffffffffu, v, o));
        if (lane == 0) sred[0] = v;
    }
    __syncthreads();
    m = sred[0];

    float ssum = 0.f;
    for (int k = tid; k < n; k += 256) {
        float e = __expf(row[k] * scale - m);
        row[k] = e;
        ssum += e;
    }
#pragma unroll
    for (int o = 16; o > 0; o >>= 1) ssum += __shfl_xor_sync(0xffffffffu, ssum, o);
    if (lane == 0) sred[wid] = ssum;
    __syncthreads();
    if (wid == 0) {
        float v = (lane < 8) ? sred[lane] : 0.f;
#pragma unroll
        for (int o = 4; o > 0; o >>= 1) v += __shfl_xor_sync(0xffffffffu, v, o);
        if (lane == 0) sred[0] = v;
    }
    __syncthreads();
    float inv = 1.f / sred[0];
    for (int k = tid; k < n; k += 256) row[k] *= inv;
    for (int k = n + tid; k < SS; k += 256) row[k] = 0.f;  // zero tail (defensive)
}

// ---------------- launch ----------------
extern "C" void kernel_launch(void* const* d_in, const int* in_sizes, int n_in,
                              void* d_out, int out_size)
{
    const float* x        = (const float*)d_in[0];
    const float* w_q_a    = (const float*)d_in[1];
    const float* q_a_ln_w = (const float*)d_in[2];
    const float* w_q_b    = (const float*)d_in[3];
    const float* w_kv_a   = (const float*)d_in[4];
    const float* kv_a_ln_w= (const float*)d_in[5];
    const float* w_kv_b   = (const float*)d_in[6];
    const float* w_o      = (const float*)d_in[7];
    float* out = (float*)d_out;

    float *p_qa, *p_q, *p_ckv, *p_kfull, *p_qfull, *p_woabs, *p_scores, *p_octx;
    cudaGetSymbolAddress((void**)&p_qa, g_qa);
    cudaGetSymbolAddress((void**)&p_q, g_q);
    cudaGetSymbolAddress((void**)&p_ckv, g_ckv_kpe);
    cudaGetSymbolAddress((void**)&p_kfull, g_kfull);
    cudaGetSymbolAddress((void**)&p_qfull, g_qfull);
    cudaGetSymbolAddress((void**)&p_woabs, g_woabs);
    cudaGetSymbolAddress((void**)&p_scores, g_scores);
    cudaGetSymbolAddress((void**)&p_octx, g_octx);

    const float sm_scale = rsqrtf((float)(DNN + DRR));

    // 1) qa_raw = x @ w_q_a   [2048x1536, K=2048]
    gemm128<false, false, false><<<dim3(12, 16, 1), 256>>>(
        x, w_q_a, p_qa, SS, QLRR, EE, EE, QLRR, QLRR, 0, 0, 0);
    // 2) rmsnorm(q_a) in place
    rmsnorm_k<<<SS, 256>>>(p_qa, q_a_ln_w, p_qa, QLRR, QLRR, QLRR);
    // 3) q = q_a @ w_q_b      [2048x3072, K=1536]
    gemm128<false, false, false><<<dim3(24, 16, 1), 256>>>(
        p_qa, w_q_b, p_q, SS, 3072, QLRR, QLRR, 3072, 3072, 0, 0, 0);
    // 4) ckv_kpe = x @ w_kv_a [2048x576, K=2048]
    gemm128<false, false, false><<<dim3(5, 16, 1), 256>>>(
        x, w_kv_a, p_ckv, SS, 576, EE, EE, 576, 576, 0, 0, 0);
    // 5) kfull[:, :512] = rmsnorm(ckv)
    rmsnorm_k<<<SS, 256>>>(p_ckv, kv_a_ln_w, p_kfull, RR, 576, 576);
    // 6) kfull[:, 512:576] = rope(k_pe)
    rope_k_kernel<<<SS, 64>>>(p_ckv, p_kfull);
    // 7) qfull[h][s][512:576] = rope(q_pe)
    rope_q_kernel<<<dim3(SS, HH), 64>>>(p_q, p_qfull);
    // 8) qfull[h][s][0:512] = q_nope @ w_uk^T   (batched NT, M=2048 N=512 K=128)
    gemm128<true, false, false><<<dim3(4, 16, HH), 256>>>(
        p_q, w_kv_b, p_qfull, SS, RR, DNN, 3072, 4096, 576,
        192LL, 256LL, (long long)SS * 576);
    // 9) w_o_abs[h] = w_uv[h]^T-absorbed gemm  (batched NN, M=512 N=2048 K=128)
    gemm128<false, false, false><<<dim3(16, 4, HH), 256>>>(
        w_kv_b + 128, w_o, p_woabs, RR, EE, DNN, 4096, EE, EE,
        256LL, (long long)DNN * EE, (long long)RR * EE);
    // 10) scores[h] = qfull[h] @ kfull^T  (batched NT, causal-skip; M=N=2048 K=576)
    gemm128<true, true, false><<<dim3(16, 16, HH), 256>>>(
        p_qfull, p_kfull, p_scores, SS, SS, 576, 576, 576, SS,
        (long long)SS * 576, 0LL, (long long)SS * SS);
    // 11) causal softmax in place (zero-fills the upper triangle)
    softmax_causal<<<dim3(SS, HH), 256>>>(p_scores, sm_scale);
    // 12) octx[s][h][:] = attn[h] @ ckv  (batched NN, causal K-limit; M=2048 N=512 K=2048)
    gemm128<false, false, true><<<dim3(4, 16, HH), 256>>>(
        p_scores, p_kfull, p_octx, SS, RR, SS, SS, 576, HH * RR,
        (long long)SS * SS, 0LL, (long long)RR);
    // 13) y = octx @ w_o_abs  (NN, M=2048 N=2048 K=8192)
    gemm128<false, false, false><<<dim3(16, 16, 1), 256>>>(
        p_octx, p_woabs, out, SS, EE, HH * RR, HH * RR, EE, EE, 0, 0, 0);
}

// round 5
// speedup vs baseline: 1.2932x; 1.2932x over previous
#include <cuda_runtime.h>
#include <mma.h>
#include <math.h>

using namespace nvcuda;

#define SS 2048
#define EE 2048
#define HH 16
#define DNN 128
#define DRR 64
#define RR 512
#define QLRR 1536

// ---------------- scratch (static device globals; no allocations) ----------------
__device__ float g_qa[SS * QLRR];
__device__ float g_q[SS * HH * (DNN + DRR)];
__device__ float g_ckv_kpe[SS * (RR + DRR)];
__device__ float g_kfull[SS * (RR + DRR)];
__device__ float g_qfull[HH * SS * (RR + DRR)];
__device__ float g_woabs[HH * RR * EE];
__device__ float g_scores[(size_t)HH * SS * SS];
__device__ float g_octx[SS * HH * RR];

// ---------------- tf32 tensor-core GEMM: C = A * B (or A * B^T) ----------------
// BM=BN=128, BK=16, 256 threads = 8 warps in 4x2; each warp does 32x64 via
// 2x4 wmma m16n16k8 tf32 tiles. Register-prefetch double buffering on gmem.
// TRANSB: B is [N,K] k-contiguous. CSKIP: skip blocks above causal diagonal.
// CKLIM: limit K loop to causal extent of this M-tile.
// Requirements (all call sites satisfy): M%128==0, K%16==0, N%16==0, N%4==0,
// all row strides %4==0, base pointers 16B-aligned.
#define ALD 20    // As row stride (floats): 80B, 16B-aligned rows
#define BLD 132   // Bs row stride (floats): 528B, 16B-aligned rows

template <bool TRANSB, bool CSKIP, bool CKLIM>
__global__ __launch_bounds__(256) void gemm_tc(
    const float* __restrict__ A, const float* __restrict__ B, float* __restrict__ C,
    int M, int N, int K, int lda, int ldb, int ldc,
    long long sA, long long sB, long long sC)
{
    int bz = blockIdx.z;
    A += sA * bz; B += sB * bz; C += sC * bz;
    int bx = blockIdx.x, by = blockIdx.y;
    if (CSKIP && bx > by) return;
    int kEnd = CKLIM ? min(K, (by + 1) * 128) : K;

    __shared__ __align__(16) float As[128 * ALD];   // [m][k]
    __shared__ __align__(16) float Bs[16 * BLD];    // [k][n]

    int tid = threadIdx.x;
    int wid = tid >> 5;
    int wr = wid >> 1;   // 0..3 : 32-row slab
    int wc = wid & 1;    // 0..1 : 64-col slab

    wmma::fragment<wmma::accumulator, 16, 16, 8, float> acc[2][4];
#pragma unroll
    for (int i = 0; i < 2; i++)
#pragma unroll
        for (int j = 0; j < 4; j++) wmma::fill_fragment(acc[i][j], 0.0f);

    // ---- staging index precompute ----
    int aRow = tid >> 1;                 // 0..127
    int aColB = (tid & 1) << 2;          // 0 or 4
    // NN B: row tid>>5 (+8), col (tid&31)*4
    int bRowN = tid >> 5;
    int bColN = (tid & 31) << 2;
    // NT B: n = tid&127, k base (tid>>7)*4
    int bnT = tid & 127;
    int bkT = (tid >> 7) << 2;

    float4 pA[2], pB[2], nA[2], nB[2];

    auto ldg = [&](int k0, float4* ra, float4* rb) {
#pragma unroll
        for (int r = 0; r < 2; r++) {
            const float* ap = A + (long long)(by * 128 + aRow) * lda + (k0 + aColB + 8 * r);
            ra[r] = *reinterpret_cast<const float4*>(ap);
        }
        if (!TRANSB) {
#pragma unroll
            for (int r = 0; r < 2; r++) {
                int gn = bx * 128 + bColN;
                if (gn < N) {
                    const float* bp = B + (long long)(k0 + bRowN + 8 * r) * ldb + gn;
                    rb[r] = *reinterpret_cast<const float4*>(bp);
                } else {
                    rb[r] = make_float4(0.f, 0.f, 0.f, 0.f);
                }
            }
        } else {
#pragma unroll
            for (int r = 0; r < 2; r++) {
                int gn = bx * 128 + bnT;
                if (gn < N) {
                    const float* bp = B + (long long)gn * ldb + (k0 + bkT + 8 * r);
                    rb[r] = *reinterpret_cast<const float4*>(bp);
                } else {
                    rb[r] = make_float4(0.f, 0.f, 0.f, 0.f);
                }
            }
        }
    };

    auto sts = [&](const float4* ra, const float4* rb) {
#pragma unroll
        for (int r = 0; r < 2; r++) {
            float* dst = &As[aRow * ALD + aColB + 8 * r];
            dst[0] = wmma::__float_to_tf32(ra[r].x);
            dst[1] = wmma::__float_to_tf32(ra[r].y);
            dst[2] = wmma::__float_to_tf32(ra[r].z);
            dst[3] = wmma::__float_to_tf32(ra[r].w);
        }
        if (!TRANSB) {
#pragma unroll
            for (int r = 0; r < 2; r++) {
                float* dst = &Bs[(bRowN + 8 * r) * BLD + bColN];
                dst[0] = wmma::__float_to_tf32(rb[r].x);
                dst[1] = wmma::__float_to_tf32(rb[r].y);
                dst[2] = wmma::__float_to_tf32(rb[r].z);
                dst[3] = wmma::__float_to_tf32(rb[r].w);
            }
        } else {
#pragma unroll
            for (int r = 0; r < 2; r++) {
                int bk = bkT + 8 * r;
                Bs[(bk + 0) * BLD + bnT] = wmma::__float_to_tf32(rb[r].x);
                Bs[(bk + 1) * BLD + bnT] = wmma::__float_to_tf32(rb[r].y);
                Bs[(bk + 2) * BLD + bnT] = wmma::__float_to_tf32(rb[r].z);
                Bs[(bk + 3) * BLD + bnT] = wmma::__float_to_tf32(rb[r].w);
            }
        }
    };

    ldg(0, pA, pB);
    for (int k0 = 0; k0 < kEnd; k0 += 16) {
        sts(pA, pB);
        __syncthreads();
        bool more = (k0 + 16) < kEnd;
        if (more) ldg(k0 + 16, nA, nB);

#pragma unroll
        for (int ks = 0; ks < 16; ks += 8) {
            wmma::fragment<wmma::matrix_a, 16, 16, 8, wmma::precision::tf32, wmma::row_major> af[2];
            wmma::fragment<wmma::matrix_b, 16, 16, 8, wmma::precision::tf32, wmma::row_major> bf[4];
#pragma unroll
            for (int i = 0; i < 2; i++)
                wmma::load_matrix_sync(af[i], &As[(wr * 32 + i * 16) * ALD + ks], ALD);
#pragma unroll
            for (int j = 0; j < 4; j++)
                wmma::load_matrix_sync(bf[j], &Bs[ks * BLD + wc * 64 + j * 16], BLD);
#pragma unroll
            for (int i = 0; i < 2; i++)
#pragma unroll
                for (int j = 0; j < 4; j++)
                    wmma::mma_sync(acc[i][j], af[i], bf[j], acc[i][j]);
        }
        __syncthreads();
        if (more) {
#pragma unroll
            for (int r = 0; r < 2; r++) { pA[r] = nA[r]; pB[r] = nB[r]; }
        }
    }

    // ---- store: tiles are fully in or out of bounds (N%16==0) ----
#pragma unroll
    for (int i = 0; i < 2; i++) {
        int m0 = by * 128 + wr * 32 + i * 16;
#pragma unroll
        for (int j = 0; j < 4; j++) {
            int n0 = bx * 128 + wc * 64 + j * 16;
            if (n0 < N)
                wmma::store_matrix_sync(C + (long long)m0 * ldc + n0, acc[i][j], ldc,
                                        wmma::mem_row_major);
        }
    }
}

// ---------------- rmsnorm over rows ----------------
__global__ __launch_bounds__(256) void rmsnorm_k(
    const float* __restrict__ in, const float* __restrict__ w, float* __restrict__ out,
    int ncols, int ldin, int ldout)
{
    int row = blockIdx.x;
    const float* ip = in + (long long)row * ldin;
    float* op = out + (long long)row * ldout;
    float ss = 0.f;
    for (int c = threadIdx.x; c < ncols; c += blockDim.x) {
        float v = ip[c];
        ss += v * v;
    }
    __shared__ float sred[32];
#pragma unroll
    for (int o = 16; o > 0; o >>= 1) ss += __shfl_xor_sync(0xffffffffu, ss, o);
    int lane = threadIdx.x & 31, wid = threadIdx.x >> 5;
    if (lane == 0) sred[wid] = ss;
    __syncthreads();
    if (wid == 0) {
        float v = (lane < 8) ? sred[lane] : 0.f;
#pragma unroll
        for (int o = 4; o > 0; o >>= 1) v += __shfl_xor_sync(0xffffffffu, v, o);
        if (lane == 0) sred[0] = v;
    }
    __syncthreads();
    float r = rsqrtf(sred[0] / (float)ncols + 1e-6f);
    for (int c = threadIdx.x; c < ncols; c += blockDim.x) op[c] = ip[c] * r * w[c];
}

// ---------------- RoPE ----------------
__device__ __forceinline__ float2 rope_cs(int pos, int i) {
    float freq = powf(10000.0f, -(float)(2 * i) / 64.0f);
    float ang = (float)pos * freq;
    float c, s;
    sincosf(ang, &s, &c);
    return make_float2(c, s);
}

__global__ void rope_k_kernel(const float* __restrict__ ckv_kpe, float* __restrict__ kfull) {
    int s = blockIdx.x, j = threadIdx.x;  // 64 threads
    const float* src = ckv_kpe + (long long)s * 576 + 512;
    float2 cs = rope_cs(s, j & 31);
    float x = src[j];
    float rot = (j < 32) ? -src[j + 32] : src[j - 32];
    kfull[(long long)s * 576 + 512 + j] = x * cs.x + rot * cs.y;
}

__global__ void rope_q_kernel(const float* __restrict__ q, float* __restrict__ qfull) {
    int s = blockIdx.x, h = blockIdx.y, j = threadIdx.x;  // 64 threads
    const float* src = q + (long long)s * 3072 + h * 192 + 128;
    float2 cs = rope_cs(s, j & 31);
    float x = src[j];
    float rot = (j < 32) ? -src[j + 32] : src[j - 32];
    qfull[((long long)h * SS + s) * 576 + 512 + j] = x * cs.x + rot * cs.y;
}

// ---------------- causal softmax (in place on scores) ----------------
__global__ __launch_bounds__(256) void softmax_causal(float* __restrict__ scores, float scale) {
    int q = blockIdx.x, h = blockIdx.y;
    float* row = scores + ((long long)h * SS + q) * SS;
    int tid = threadIdx.x;
    int n = q + 1;

    float m = -1e30f;
    for (int k = tid; k < n; k += 256) m = fmaxf(m, row[k] * scale);
    __shared__ float sred[32];
#pragma unroll
    for (int o = 16; o > 0; o >>= 1) m = fmaxf(m, __shfl_xor_sync(0xffffffffu, m, o));
    int lane = tid & 31, wid = tid >> 5;
    if (lane == 0) sred[wid] = m;
    __syncthreads();
    if (wid == 0) {
        float v = (lane < 8) ? sred[lane] : -1e30f;
#pragma unroll
        for (int o = 4; o > 0; o >>= 1) v = fmaxf(v, __shfl_xor_sync(0xffffffffu, v, o));
        if (lane == 0) sred[0] = v;
    }
    __syncthreads();
    m = sred[0];

    float ssum = 0.f;
    for (int k = tid; k < n; k += 256) {
        float e = __expf(row[k] * scale - m);
        row[k] = e;
        ssum += e;
    }
#pragma unroll
    for (int o = 16; o > 0; o >>= 1) ssum += __shfl_xor_sync(0xffffffffu, ssum, o);
    if (lane == 0) sred[wid] = ssum;
    __syncthreads();
    if (wid == 0) {
        float v = (lane < 8) ? sred[lane] : 0.f;
#pragma unroll
        for (int o = 4; o > 0; o >>= 1) v += __shfl_xor_sync(0xffffffffu, v, o);
        if (lane == 0) sred[0] = v;
    }
    __syncthreads();
    float inv = 1.f / sred[0];
    for (int k = tid; k < n; k += 256) row[k] *= inv;
    for (int k = n + tid; k < SS; k += 256) row[k] = 0.f;  // zero tail (defensive)
}

// ---------------- launch ----------------
extern "C" void kernel_launch(void* const* d_in, const int* in_sizes, int n_in,
                              void* d_out, int out_size)
{
    const float* x        = (const float*)d_in[0];
    const float* w_q_a    = (const float*)d_in[1];
    const float* q_a_ln_w = (const float*)d_in[2];
    const float* w_q_b    = (const float*)d_in[3];
    const float* w_kv_a   = (const float*)d_in[4];
    const float* kv_a_ln_w= (const float*)d_in[5];
    const float* w_kv_b   = (const float*)d_in[6];
    const float* w_o      = (const float*)d_in[7];
    float* out = (float*)d_out;

    float *p_qa, *p_q, *p_ckv, *p_kfull, *p_qfull, *p_woabs, *p_scores, *p_octx;
    cudaGetSymbolAddress((void**)&p_qa, g_qa);
    cudaGetSymbolAddress((void**)&p_q, g_q);
    cudaGetSymbolAddress((void**)&p_ckv, g_ckv_kpe);
    cudaGetSymbolAddress((void**)&p_kfull, g_kfull);
    cudaGetSymbolAddress((void**)&p_qfull, g_qfull);
    cudaGetSymbolAddress((void**)&p_woabs, g_woabs);
    cudaGetSymbolAddress((void**)&p_scores, g_scores);
    cudaGetSymbolAddress((void**)&p_octx, g_octx);

    const float sm_scale = rsqrtf((float)(DNN + DRR));

    // 1) qa_raw = x @ w_q_a   [2048x1536, K=2048]
    gemm_tc<false, false, false><<<dim3(12, 16, 1), 256>>>(
        x, w_q_a, p_qa, SS, QLRR, EE, EE, QLRR, QLRR, 0, 0, 0);
    // 2) rmsnorm(q_a) in place
    rmsnorm_k<<<SS, 256>>>(p_qa, q_a_ln_w, p_qa, QLRR, QLRR, QLRR);
    // 3) q = q_a @ w_q_b      [2048x3072, K=1536]
    gemm_tc<false, false, false><<<dim3(24, 16, 1), 256>>>(
        p_qa, w_q_b, p_q, SS, 3072, QLRR, QLRR, 3072, 3072, 0, 0, 0);
    // 4) ckv_kpe = x @ w_kv_a [2048x576, K=2048]
    gemm_tc<false, false, false><<<dim3(5, 16, 1), 256>>>(
        x, w_kv_a, p_ckv, SS, 576, EE, EE, 576, 576, 0, 0, 0);
    // 5) kfull[:, :512] = rmsnorm(ckv)
    rmsnorm_k<<<SS, 256>>>(p_ckv, kv_a_ln_w, p_kfull, RR, 576, 576);
    // 6) kfull[:, 512:576] = rope(k_pe)
    rope_k_kernel<<<SS, 64>>>(p_ckv, p_kfull);
    // 7) qfull[h][s][512:576] = rope(q_pe)
    rope_q_kernel<<<dim3(SS, HH), 64>>>(p_q, p_qfull);
    // 8) qfull[h][s][0:512] = q_nope @ w_uk^T   (batched NT, M=2048 N=512 K=128)
    gemm_tc<true, false, false><<<dim3(4, 16, HH), 256>>>(
        p_q, w_kv_b, p_qfull, SS, RR, DNN, 3072, 4096, 576,
        192LL, 256LL, (long long)SS * 576);
    // 9) w_o_abs[h] = w_uv[h]^T @ w_o[h]  (batched NN, M=512 N=2048 K=128)
    gemm_tc<false, false, false><<<dim3(16, 4, HH), 256>>>(
        w_kv_b + 128, w_o, p_woabs, RR, EE, DNN, 4096, EE, EE,
        256LL, (long long)DNN * EE, (long long)RR * EE);
    // 10) scores[h] = qfull[h] @ kfull^T  (batched NT, causal-skip; M=N=2048 K=576)
    gemm_tc<true, true, false><<<dim3(16, 16, HH), 256>>>(
        p_qfull, p_kfull, p_scores, SS, SS, 576, 576, 576, SS,
        (long long)SS * 576, 0LL, (long long)SS * SS);
    // 11) causal softmax in place (zero-fills the upper triangle)
    softmax_causal<<<dim3(SS, HH), 256>>>(p_scores, sm_scale);
    // 12) octx[s][h][:] = attn[h] @ ckv  (batched NN, causal K-limit; M=2048 N=512 K=2048)
    gemm_tc<false, false, true><<<dim3(4, 16, HH), 256>>>(
        p_scores, p_kfull, p_octx, SS, RR, SS, SS, 576, HH * RR,
        (long long)SS * SS, 0LL, (long long)RR);
    // 13) y = octx @ w_o_abs  (NN, M=2048 N=2048 K=8192)
    gemm_tc<false, false, false><<<dim3(16, 16, 1), 256>>>(
        p_octx, p_woabs, out, SS, EE, HH * RR, HH * RR, EE, EE, 0, 0, 0);
}

// round 7
// speedup vs baseline: 1.4926x; 1.1542x over previous
#include <cuda_runtime.h>
#include <cuda_bf16.h>
#include <mma.h>
#include <math.h>

using namespace nvcuda;
typedef __nv_bfloat16 bf16;

#define SS 2048
#define EE 2048
#define HH 16
#define DNN 128
#define DRR 64
#define RR 512
#define QLRR 1536

// ---------------- scratch (static device globals; no allocations) ----------------
__device__ float g_qa[SS * QLRR];
__device__ float g_q[SS * HH * (DNN + DRR)];
__device__ float g_ckv_kpe[SS * (RR + DRR)];
__device__ float g_kfull[SS * (RR + DRR)];
__device__ float g_qfull[HH * SS * (RR + DRR)];
__device__ float g_woabs[HH * RR * EE];
__device__ float g_scores[(size_t)HH * SS * SS];
__device__ float g_octx[SS * HH * RR];

// ---------------- bf16-split tensor-core GEMM: C = A * B (or A * B^T) ----------------
// Each fp32 input is split x = hi + lo (both bf16); the product uses
// Ah*Bh + Ah*Bl + Al*Bh with fp32 accumulation -> ~2^-18 effective input error.
// BM=BN=128, BK=16, 256 threads = 8 warps (4x2); warp tile 32x64 via 2x4
// m16n16k16 fragments. 2-stage smem double buffering, ONE barrier per BK iter.
// TRANSB: B is [N,K] k-contiguous. CSKIP: skip blocks above causal diagonal.
// CKLIM: limit K loop to causal extent of this M-tile.
// Call-site requirements: M%128==0, K%16==0, N%16==0, strides %4==0, 16B-aligned.
#define AKLD 24    // A smem k-stride (elems, %8==0 for wmma ldm)
#define BNLD 136   // B smem n-stride (elems, %8==0)

__device__ __forceinline__ void bsplit(float v, bf16& h, bf16& l) {
    h = __float2bfloat16(v);
    l = __float2bfloat16(v - __bfloat162float(h));
}

template <bool TRANSB, bool CSKIP, bool CKLIM>
__global__ __launch_bounds__(256) void gemm_tc(
    const float* __restrict__ A, const float* __restrict__ B, float* __restrict__ C,
    int M, int N, int K, int lda, int ldb, int ldc,
    long long sA, long long sB, long long sC)
{
    int bz = blockIdx.z;
    A += sA * bz; B += sB * bz; C += sC * bz;
    int bx = blockIdx.x, by = blockIdx.y;
    if (CSKIP && bx > by) return;
    int kEnd = CKLIM ? min(K, (by + 1) * 128) : K;   // always a multiple of 16 here

    __shared__ __align__(16) bf16 sAh[2][128 * AKLD];
    __shared__ __align__(16) bf16 sAl[2][128 * AKLD];
    __shared__ __align__(16) bf16 sBh[2][16 * BNLD];
    __shared__ __align__(16) bf16 sBl[2][16 * BNLD];

    int tid = threadIdx.x;
    int wid = tid >> 5;
    int wr = wid >> 1;   // 0..3 : 32-row slab
    int wc = wid & 1;    // 0..1 : 64-col slab

    wmma::fragment<wmma::accumulator, 16, 16, 16, float> acc[2][4];
#pragma unroll
    for (int i = 0; i < 2; i++)
#pragma unroll
        for (int j = 0; j < 4; j++) wmma::fill_fragment(acc[i][j], 0.0f);

    // ---- staging indices ----
    int aRow = tid >> 1;                 // 0..127
    int aColB = (tid & 1) << 2;          // 0 or 4
    int bRowN = tid >> 5;                // NN: k row 0..7 (+8)
    int bColN = (tid & 31) << 2;         // NN: n col
    int bnT = tid & 127;                 // NT: n row
    int bkT = (tid >> 7) << 2;           // NT: k base 0 or 4

    float4 rA[2], rB[2];

    auto ldg = [&](int k0) {
#pragma unroll
        for (int r = 0; r < 2; r++) {
            const float* ap = A + (long long)(by * 128 + aRow) * lda + (k0 + aColB + 8 * r);
            rA[r] = *reinterpret_cast<const float4*>(ap);
        }
        if (!TRANSB) {
#pragma unroll
            for (int r = 0; r < 2; r++) {
                int gn = bx * 128 + bColN;
                if (gn < N) {
                    const float* bp = B + (long long)(k0 + bRowN + 8 * r) * ldb + gn;
                    rB[r] = *reinterpret_cast<const float4*>(bp);
                } else {
                    rB[r] = make_float4(0.f, 0.f, 0.f, 0.f);
                }
            }
        } else {
#pragma unroll
            for (int r = 0; r < 2; r++) {
                int gn = bx * 128 + bnT;
                if (gn < N) {
                    const float* bp = B + (long long)gn * ldb + (k0 + bkT + 8 * r);
                    rB[r] = *reinterpret_cast<const float4*>(bp);
                } else {
                    rB[r] = make_float4(0.f, 0.f, 0.f, 0.f);
                }
            }
        }
    };

    auto sts = [&](int st) {
#pragma unroll
        for (int r = 0; r < 2; r++) {
            int base = aRow * AKLD + aColB + 8 * r;
            const float v[4] = {rA[r].x, rA[r].y, rA[r].z, rA[r].w};
#pragma unroll
            for (int c = 0; c < 4; c++) {
                bf16 h, l; bsplit(v[c], h, l);
                sAh[st][base + c] = h;
                sAl[st][base + c] = l;
            }
        }
        if (!TRANSB) {
#pragma unroll
            for (int r = 0; r < 2; r++) {
                int base = (bRowN + 8 * r) * BNLD + bColN;
                const float v[4] = {rB[r].x, rB[r].y, rB[r].z, rB[r].w};
#pragma unroll
                for (int c = 0; c < 4; c++) {
                    bf16 h, l; bsplit(v[c], h, l);
                    sBh[st][base + c] = h;
                    sBl[st][base + c] = l;
                }
            }
        } else {
#pragma unroll
            for (int r = 0; r < 2; r++) {
                int bk = bkT + 8 * r;
                const float v[4] = {rB[r].x, rB[r].y, rB[r].z, rB[r].w};
#pragma unroll
                for (int c = 0; c < 4; c++) {
                    bf16 h, l; bsplit(v[c], h, l);
                    sBh[st][(bk + c) * BNLD + bnT] = h;
                    sBl[st][(bk + c) * BNLD + bnT] = l;
                }
            }
        }
    };

    ldg(0);
    sts(0);
    __syncthreads();

    int nIter = kEnd >> 4;
    for (int it = 0; it < nIter; it++) {
        int st = it & 1;
        bool more = (it + 1) < nIter;
        if (more) ldg((it + 1) << 4);

        wmma::fragment<wmma::matrix_a, 16, 16, 16, bf16, wmma::row_major> ah[2], al[2];
        wmma::fragment<wmma::matrix_b, 16, 16, 16, bf16, wmma::row_major> bh[4], bl[4];
#pragma unroll
        for (int i = 0; i < 2; i++) {
            int m0 = (wr * 32 + i * 16) * AKLD;
            wmma::load_matrix_sync(ah[i], &sAh[st][m0], AKLD);
            wmma::load_matrix_sync(al[i], &sAl[st][m0], AKLD);
        }
#pragma unroll
        for (int j = 0; j < 4; j++) {
            int n0 = wc * 64 + j * 16;
            wmma::load_matrix_sync(bh[j], &sBh[st][n0], BNLD);
            wmma::load_matrix_sync(bl[j], &sBl[st][n0], BNLD);
        }
#pragma unroll
        for (int i = 0; i < 2; i++)
#pragma unroll
            for (int j = 0; j < 4; j++) {
                wmma::mma_sync(acc[i][j], ah[i], bh[j], acc[i][j]);
                wmma::mma_sync(acc[i][j], ah[i], bl[j], acc[i][j]);
                wmma::mma_sync(acc[i][j], al[i], bh[j], acc[i][j]);
            }

        if (more) {
            sts(st ^ 1);
            __syncthreads();
        }
    }

    // ---- store: tiles fully in or out of bounds (N%16==0) ----
#pragma unroll
    for (int i = 0; i < 2; i++) {
        int m0 = by * 128 + wr * 32 + i * 16;
#pragma unroll
        for (int j = 0; j < 4; j++) {
            int n0 = bx * 128 + wc * 64 + j * 16;
            if (n0 < N)
                wmma::store_matrix_sync(C + (long long)m0 * ldc + n0, acc[i][j], ldc,
                                        wmma::mem_row_major);
        }
    }
}

// ---------------- rmsnorm over rows ----------------
__global__ __launch_bounds__(256) void rmsnorm_k(
    const float* __restrict__ in, const float* __restrict__ w, float* __restrict__ out,
    int ncols, int ldin, int ldout)
{
    int row = blockIdx.x;
    const float* ip = in + (long long)row * ldin;
    float* op = out + (long long)row * ldout;
    float ss = 0.f;
    for (int c = threadIdx.x; c < ncols; c += blockDim.x) {
        float v = ip[c];
        ss += v * v;
    }
    __shared__ float sred[32];
#pragma unroll
    for (int o = 16; o > 0; o >>= 1) ss += __shfl_xor_sync(0xffffffffu, ss, o);
    int lane = threadIdx.x & 31, wid = threadIdx.x >> 5;
    if (lane == 0) sred[wid] = ss;
    __syncthreads();
    if (wid == 0) {
        float v = (lane < 8) ? sred[lane] : 0.f;
#pragma unroll
        for (int o = 4; o > 0; o >>= 1) v += __shfl_xor_sync(0xffffffffu, v, o);
        if (lane == 0) sred[0] = v;
    }
    __syncthreads();
    float r = rsqrtf(sred[0] / (float)ncols + 1e-6f);
    for (int c = threadIdx.x; c < ncols; c += blockDim.x) op[c] = ip[c] * r * w[c];
}

// ---------------- RoPE ----------------
__device__ __forceinline__ float2 rope_cs(int pos, int i) {
    float freq = powf(10000.0f, -(float)(2 * i) / 64.0f);
    float ang = (float)pos * freq;
    float c, s;
    sincosf(ang, &s, &c);
    return make_float2(c, s);
}

__global__ void rope_k_kernel(const float* __restrict__ ckv_kpe, float* __restrict__ kfull) {
    int s = blockIdx.x, j = threadIdx.x;  // 64 threads
    const float* src = ckv_kpe + (long long)s * 576 + 512;
    float2 cs = rope_cs(s, j & 31);
    float x = src[j];
    float rot = (j < 32) ? -src[j + 32] : src[j - 32];
    kfull[(long long)s * 576 + 512 + j] = x * cs.x + rot * cs.y;
}

__global__ void rope_q_kernel(const float* __restrict__ q, float* __restrict__ qfull) {
    int s = blockIdx.x, h = blockIdx.y, j = threadIdx.x;  // 64 threads
    const float* src = q + (long long)s * 3072 + h * 192 + 128;
    float2 cs = rope_cs(s, j & 31);
    float x = src[j];
    float rot = (j < 32) ? -src[j + 32] : src[j - 32];
    qfull[((long long)h * SS + s) * 576 + 512 + j] = x * cs.x + rot * cs.y;
}

// ---------------- causal softmax (in place on scores) ----------------
__global__ __launch_bounds__(256) void softmax_causal(float* __restrict__ scores, float scale) {
    int q = blockIdx.x, h = blockIdx.y;
    float* row = scores + ((long long)h * SS + q) * SS;
    int tid = threadIdx.x;
    int n = q + 1;

    float m = -1e30f;
    for (int k = tid; k < n; k += 256) m = fmaxf(m, row[k] * scale);
    __shared__ float sred[32];
#pragma unroll
    for (int o = 16; o > 0; o >>= 1) m = fmaxf(m, __shfl_xor_sync(0xffffffffu, m, o));
    int lane = tid & 31, wid = tid >> 5;
    if (lane == 0) sred[wid] = m;
    __syncthreads();
    if (wid == 0) {
        float v = (lane < 8) ? sred[lane] : -1e30f;
#pragma unroll
        for (int o = 4; o > 0; o >>= 1) v = fmaxf(v, __shfl_xor_sync(0xffffffffu, v, o));
        if (lane == 0) sred[0] = v;
    }
    __syncthreads();
    m = sred[0];

    float ssum = 0.f;
    for (int k = tid; k < n; k += 256) {
        float e = __expf(row[k] * scale - m);
        row[k] = e;
        ssum += e;
    }
#pragma unroll
    for (int o = 16; o > 0; o >>= 1) ssum += __shfl_xor_sync(0xffffffffu, ssum, o);
    if (lane == 0) sred[wid] = ssum;
    __syncthreads();
    if (wid == 0) {
        float v = (lane < 8) ? sred[lane] : 0.f;
#pragma unroll
        for (int o = 4; o > 0; o >>= 1) v += __shfl_xor_sync(0xffffffffu, v, o);
        if (lane == 0) sred[0] = v;
    }
    __syncthreads();
    float inv = 1.f / sred[0];
    for (int k = tid; k < n; k += 256) row[k] *= inv;
    for (int k = n + tid; k < SS; k += 256) row[k] = 0.f;  // zero tail (defensive)
}

// ---------------- launch ----------------
extern "C" void kernel_launch(void* const* d_in, const int* in_sizes, int n_in,
                              void* d_out, int out_size)
{
    const float* x        = (const float*)d_in[0];
    const float* w_q_a    = (const float*)d_in[1];
    const float* q_a_ln_w = (const float*)d_in[2];
    const float* w_q_b    = (const float*)d_in[3];
    const float* w_kv_a   = (const float*)d_in[4];
    const float* kv_a_ln_w= (const float*)d_in[5];
    const float* w_kv_b   = (const float*)d_in[6];
    const float* w_o      = (const float*)d_in[7];
    float* out = (float*)d_out;

    float *p_qa, *p_q, *p_ckv, *p_kfull, *p_qfull, *p_woabs, *p_scores, *p_octx;
    cudaGetSymbolAddress((void**)&p_qa, g_qa);
    cudaGetSymbolAddress((void**)&p_q, g_q);
    cudaGetSymbolAddress((void**)&p_ckv, g_ckv_kpe);
    cudaGetSymbolAddress((void**)&p_kfull, g_kfull);
    cudaGetSymbolAddress((void**)&p_qfull, g_qfull);
    cudaGetSymbolAddress((void**)&p_woabs, g_woabs);
    cudaGetSymbolAddress((void**)&p_scores, g_scores);
    cudaGetSymbolAddress((void**)&p_octx, g_octx);

    const float sm_scale = rsqrtf((float)(DNN + DRR));

    // 1) qa_raw = x @ w_q_a   [2048x1536, K=2048]
    gemm_tc<false, false, false><<<dim3(12, 16, 1), 256>>>(
        x, w_q_a, p_qa, SS, QLRR, EE, EE, QLRR, QLRR, 0, 0, 0);
    // 2) rmsnorm(q_a) in place
    rmsnorm_k<<<SS, 256>>>(p_qa, q_a_ln_w, p_qa, QLRR, QLRR, QLRR);
    // 3) q = q_a @ w_q_b      [2048x3072, K=1536]
    gemm_tc<false, false, false><<<dim3(24, 16, 1), 256>>>(
        p_qa, w_q_b, p_q, SS, 3072, QLRR, QLRR, 3072, 3072, 0, 0, 0);
    // 4) ckv_kpe = x @ w_kv_a [2048x576, K=2048]
    gemm_tc<false, false, false><<<dim3(5, 16, 1), 256>>>(
        x, w_kv_a, p_ckv, SS, 576, EE, EE, 576, 576, 0, 0, 0);
    // 5) kfull[:, :512] = rmsnorm(ckv)
    rmsnorm_k<<<SS, 256>>>(p_ckv, kv_a_ln_w, p_kfull, RR, 576, 576);
    // 6) kfull[:, 512:576] = rope(k_pe)
    rope_k_kernel<<<SS, 64>>>(p_ckv, p_kfull);
    // 7) qfull[h][s][512:576] = rope(q_pe)
    rope_q_kernel<<<dim3(SS, HH), 64>>>(p_q, p_qfull);
    // 8) qfull[h][s][0:512] = q_nope @ w_uk^T   (batched NT, M=2048 N=512 K=128)
    gemm_tc<true, false, false><<<dim3(4, 16, HH), 256>>>(
        p_q, w_kv_b, p_qfull, SS, RR, DNN, 3072, 4096, 576,
        192LL, 256LL, (long long)SS * 576);
    // 9) w_o_abs[h] = w_uv[h]^T @ w_o[h]  (batched NN, M=512 N=2048 K=128)
    gemm_tc<false, false, false><<<dim3(16, 4, HH), 256>>>(
        w_kv_b + 128, w_o, p_woabs, RR, EE, DNN, 4096, EE, EE,
        256LL, (long long)DNN * EE, (long long)RR * EE);
    // 10) scores[h] = qfull[h] @ kfull^T  (batched NT, causal-skip; M=N=2048 K=576)
    gemm_tc<true, true, false><<<dim3(16, 16, HH), 256>>>(
        p_qfull, p_kfull, p_scores, SS, SS, 576, 576, 576, SS,
        (long long)SS * 576, 0LL, (long long)SS * SS);
    // 11) causal softmax in place (zero-fills the upper triangle)
    softmax_causal<<<dim3(SS, HH), 256>>>(p_scores, sm_scale);
    // 12) octx[s][h][:] = attn[h] @ ckv  (batched NN, causal K-limit; M=2048 N=512 K=2048)
    gemm_tc<false, false, true><<<dim3(4, 16, HH), 256>>>(
        p_scores, p_kfull, p_octx, SS, RR, SS, SS, 576, HH * RR,
        (long long)SS * SS, 0LL, (long long)RR);
    // 13) y = octx @ w_o_abs  (NN, M=2048 N=2048 K=8192)
    gemm_tc<false, false, false><<<dim3(16, 16, 1), 256>>>(
        p_octx, p_woabs, out, SS, EE, HH * RR, HH * RR, EE, EE, 0, 0, 0);
}

// round 8
// speedup vs baseline: 2.1026x; 1.4086x over previous
#include <cuda_runtime.h>
#include <cuda_bf16.h>
#include <mma.h>
#include <math.h>

using namespace nvcuda;
typedef __nv_bfloat16 bf16;

#define SS 2048
#define EE 2048
#define HH 16
#define DNN 128
#define DRR 64
#define RR 512
#define QLRR 1536

// ---------------- fp32 scratch ----------------
__device__ float g_qa[SS * QLRR];
__device__ float g_ckv[SS * (RR + DRR)];
__device__ float g_scores[(size_t)HH * SS * SS];

// ---------------- bf16 hi/lo planes ----------------
__device__ bf16 g_x_h[SS * EE],          g_x_l[SS * EE];
__device__ bf16 g_wqa_h[EE * QLRR],      g_wqa_l[EE * QLRR];
__device__ bf16 g_qa_h[SS * QLRR],       g_qa_l[SS * QLRR];
__device__ bf16 g_wqb_h[QLRR * 3072],    g_wqb_l[QLRR * 3072];
__device__ bf16 g_q_h[SS * 3072],        g_q_l[SS * 3072];
__device__ bf16 g_wkva_h[EE * 576],      g_wkva_l[EE * 576];
__device__ bf16 g_kfull_h[SS * 576],     g_kfull_l[SS * 576];
__device__ bf16 g_wkvb_h[RR * 4096],     g_wkvb_l[RR * 4096];
__device__ bf16 g_wo_h[2048 * 2048],     g_wo_l[2048 * 2048];
__device__ bf16 g_qfull_h[HH * SS * 576], g_qfull_l[HH * SS * 576];
__device__ bf16 g_woabs_h[HH * RR * EE],  g_woabs_l[HH * RR * EE];
__device__ bf16 g_attn_h[(size_t)HH * SS * SS], g_attn_l[(size_t)HH * SS * SS];
__device__ bf16 g_octx_h[SS * HH * RR],   g_octx_l[SS * HH * RR];

__device__ __forceinline__ void bsplit(float v, bf16& h, bf16& l) {
    h = __float2bfloat16(v);
    l = __float2bfloat16(v - __bfloat162float(h));
}

// ---------------- cp.async helpers ----------------
__device__ __forceinline__ void cpa16(void* sdst, const void* gsrc, bool pred) {
    unsigned s = (unsigned)__cvta_generic_to_shared(sdst);
    int sz = pred ? 16 : 0;
    asm volatile("cp.async.cg.shared.global [%0], [%1], 16, %2;\n"
                 :: "r"(s), "l"(gsrc), "r"(sz));
}
__device__ __forceinline__ void cp_commit() { asm volatile("cp.async.commit_group;\n"); }
__device__ __forceinline__ void cp_wait1()  { asm volatile("cp.async.wait_group 1;\n" ::: "memory"); }

// ---------------- bf16-split GEMM with cp.async pipeline ----------------
// Inputs are pre-split hi/lo bf16 planes. acc += Ah*Bh + Ah*Bl + Al*Bh (fp32 acc).
// BM=BN=128, BK=32, 256 thr = 8 warps (4x2), warp tile 32x64 (2x4 m16n16k16).
// 2-stage cp.async double buffering. TRANSB: B planes are [N][K] k-contig,
// consumed via col_major fragments (no transpose needed).
// OUTSPLIT: write hi/lo bf16 planes via smem roundtrip; else fp32 C.
// Reqs: M%128==0, K%32==0, N%8==0 (N%16 for fp32-out guard), strides %8==0.
#define ALD2 40     // k-stride for A / NT-B smem rows (elems)
#define BLD2 136    // n-stride for NN-B smem rows (elems)
#define PLANE 5120  // max plane elems per stage (128*40)
#define SMEM_BYTES (2 * 4 * PLANE * 2)   // 81920

extern __shared__ bf16 dsm[];

template <bool TRANSB, bool CSKIP, bool CKLIM, bool OUTSPLIT>
__global__ __launch_bounds__(256) void gemm_bs(
    const bf16* __restrict__ Ah, const bf16* __restrict__ Al,
    const bf16* __restrict__ Bh, const bf16* __restrict__ Bl,
    float* __restrict__ C, bf16* __restrict__ Ch, bf16* __restrict__ Cl,
    int M, int N, int K, int lda, int ldb, int ldc,
    long long sA, long long sB, long long sC)
{
    int bz = blockIdx.z;
    Ah += sA * bz; Al += sA * bz; Bh += sB * bz; Bl += sB * bz;
    if (OUTSPLIT) { Ch += sC * bz; Cl += sC * bz; } else { C += sC * bz; }
    int bx = blockIdx.x, by = blockIdx.y;
    if (CSKIP && bx > by) return;
    int kEnd = CKLIM ? min(K, (by + 1) * 128) : K;   // multiple of 32

    int tid = threadIdx.x;
    int wid = tid >> 5;
    int wr = wid >> 1;   // 0..3
    int wc = wid & 1;    // 0..1

    wmma::fragment<wmma::accumulator, 16, 16, 16, float> acc[2][4];
#pragma unroll
    for (int i = 0; i < 2; i++)
#pragma unroll
        for (int j = 0; j < 4; j++) wmma::fill_fragment(acc[i][j], 0.0f);

    auto ldg = [&](int it, int st) {
        int k0 = it << 5;
        bf16* base = dsm + st * 4 * PLANE;
        bf16* sAh = base;         bf16* sAl = base + PLANE;
        bf16* sBh = base + 2 * PLANE; bf16* sBl = base + 3 * PLANE;
#pragma unroll
        for (int r = 0; r < 2; r++) {
            int c = tid * 2 + r;            // 0..511
            int row = c >> 2, kc = (c & 3) << 3;
            size_t go = (size_t)(by * 128 + row) * lda + k0 + kc;
            cpa16(sAh + row * ALD2 + kc, Ah + go, true);
            cpa16(sAl + row * ALD2 + kc, Al + go, true);
        }
        if (!TRANSB) {
#pragma unroll
            for (int r = 0; r < 2; r++) {
                int c = tid * 2 + r;
                int row = c >> 4, nc = (c & 15) << 3;
                int gn = bx * 128 + nc;
                bool p = gn < N;
                size_t go = p ? ((size_t)(k0 + row) * ldb + gn) : 0;
                cpa16(sBh + row * BLD2 + nc, Bh + go, p);
                cpa16(sBl + row * BLD2 + nc, Bl + go, p);
            }
        } else {
#pragma unroll
            for (int r = 0; r < 2; r++) {
                int c = tid * 2 + r;
                int row = c >> 2, kc = (c & 3) << 3;
                int gn = bx * 128 + row;
                bool p = gn < N;
                size_t go = p ? ((size_t)gn * ldb + k0 + kc) : 0;
                cpa16(sBh + row * ALD2 + kc, Bh + go, p);
                cpa16(sBl + row * ALD2 + kc, Bl + go, p);
            }
        }
    };

    int nIter = kEnd >> 5;
    ldg(0, 0); cp_commit();
    if (nIter > 1) ldg(1, 1);
    cp_commit();
    cp_wait1(); __syncthreads();

    for (int it = 0; it < nIter; it++) {
        int st = it & 1;
        bf16* base = dsm + st * 4 * PLANE;
        bf16* sAh = base;             bf16* sAl = base + PLANE;
        bf16* sBh = base + 2 * PLANE; bf16* sBl = base + 3 * PLANE;

#pragma unroll
        for (int kc = 0; kc < 32; kc += 16) {
            wmma::fragment<wmma::matrix_a, 16, 16, 16, bf16, wmma::row_major> ah[2], al[2];
#pragma unroll
            for (int i = 0; i < 2; i++) {
                int m0 = (wr * 32 + i * 16) * ALD2 + kc;
                wmma::load_matrix_sync(ah[i], sAh + m0, ALD2);
                wmma::load_matrix_sync(al[i], sAl + m0, ALD2);
            }
            if (!TRANSB) {
                wmma::fragment<wmma::matrix_b, 16, 16, 16, bf16, wmma::row_major> bh[4], bl[4];
#pragma unroll
                for (int j = 0; j < 4; j++) {
                    int n0 = kc * BLD2 + wc * 64 + j * 16;
                    wmma::load_matrix_sync(bh[j], sBh + n0, BLD2);
                    wmma::load_matrix_sync(bl[j], sBl + n0, BLD2);
                }
#pragma unroll
                for (int i = 0; i < 2; i++)
#pragma unroll
                    for (int j = 0; j < 4; j++) {
                        wmma::mma_sync(acc[i][j], ah[i], bh[j], acc[i][j]);
                        wmma::mma_sync(acc[i][j], ah[i], bl[j], acc[i][j]);
                        wmma::mma_sync(acc[i][j], al[i], bh[j], acc[i][j]);
                    }
            } else {
                wmma::fragment<wmma::matrix_b, 16, 16, 16, bf16, wmma::col_major> bh[4], bl[4];
#pragma unroll
                for (int j = 0; j < 4; j++) {
                    int n0 = (wc * 64 + j * 16) * ALD2 + kc;
                    wmma::load_matrix_sync(bh[j], sBh + n0, ALD2);
                    wmma::load_matrix_sync(bl[j], sBl + n0, ALD2);
                }
#pragma unroll
                for (int i = 0; i < 2; i++)
#pragma unroll
                    for (int j = 0; j < 4; j++) {
                        wmma::mma_sync(acc[i][j], ah[i], bh[j], acc[i][j]);
                        wmma::mma_sync(acc[i][j], ah[i], bl[j], acc[i][j]);
                        wmma::mma_sync(acc[i][j], al[i], bh[j], acc[i][j]);
                    }
            }
        }

        __syncthreads();
        if (it + 2 < nIter) ldg(it + 2, st);
        cp_commit();
        cp_wait1(); __syncthreads();
    }

    if (!OUTSPLIT) {
#pragma unroll
        for (int i = 0; i < 2; i++) {
            int m0 = by * 128 + wr * 32 + i * 16;
#pragma unroll
            for (int j = 0; j < 4; j++) {
                int n0 = bx * 128 + wc * 64 + j * 16;
                if (n0 < N)
                    wmma::store_matrix_sync(C + (size_t)m0 * ldc + n0, acc[i][j], ldc,
                                            wmma::mem_row_major);
            }
        }
    } else {
        float* sC = reinterpret_cast<float*>(dsm);
        __syncthreads();
#pragma unroll
        for (int i = 0; i < 2; i++)
#pragma unroll
            for (int j = 0; j < 4; j++)
                wmma::store_matrix_sync(&sC[(wr * 32 + i * 16) * 128 + wc * 64 + j * 16],
                                        acc[i][j], 128, wmma::mem_row_major);
        __syncthreads();
        int row = tid >> 1;
        int colbase = (tid & 1) << 6;
        size_t rbase = (size_t)(by * 128 + row) * ldc;
#pragma unroll
        for (int v = 0; v < 16; v++) {
            int cc = colbase + v * 4;
            int gn = bx * 128 + cc;
            if (gn < N) {
                float4 f = *reinterpret_cast<const float4*>(&sC[row * 128 + cc]);
                bf16 h[4], l[4];
                bsplit(f.x, h[0], l[0]); bsplit(f.y, h[1], l[1]);
                bsplit(f.z, h[2], l[2]); bsplit(f.w, h[3], l[3]);
                *reinterpret_cast<uint2*>(Ch + rbase + gn) = *reinterpret_cast<uint2*>(h);
                *reinterpret_cast<uint2*>(Cl + rbase + gn) = *reinterpret_cast<uint2*>(l);
            }
        }
    }
}

// ---------------- fp32 -> hi/lo split (vectorized) ----------------
__global__ __launch_bounds__(256) void split4_k(
    const float* __restrict__ in, bf16* __restrict__ h, bf16* __restrict__ l, int n4)
{
    int i = blockIdx.x * 256 + threadIdx.x;
    if (i < n4) {
        float4 f = reinterpret_cast<const float4*>(in)[i];
        bf16 hh[4], ll[4];
        bsplit(f.x, hh[0], ll[0]); bsplit(f.y, hh[1], ll[1]);
        bsplit(f.z, hh[2], ll[2]); bsplit(f.w, hh[3], ll[3]);
        reinterpret_cast<uint2*>(h)[i] = *reinterpret_cast<uint2*>(hh);
        reinterpret_cast<uint2*>(l)[i] = *reinterpret_cast<uint2*>(ll);
    }
}

// ---------------- rmsnorm: fp32 in -> hi/lo bf16 out ----------------
__global__ __launch_bounds__(256) void rmsnorm_k(
    const float* __restrict__ in, const float* __restrict__ w,
    bf16* __restrict__ oh, bf16* __restrict__ ol,
    int ncols, int ldin, int ldout)
{
    int row = blockIdx.x;
    const float* ip = in + (size_t)row * ldin;
    float ss = 0.f;
    for (int c = threadIdx.x; c < ncols; c += blockDim.x) {
        float v = ip[c];
        ss += v * v;
    }
    __shared__ float sred[32];
#pragma unroll
    for (int o = 16; o > 0; o >>= 1) ss += __shfl_xor_sync(0xffffffffu, ss, o);
    int lane = threadIdx.x & 31, wid = threadIdx.x >> 5;
    if (lane == 0) sred[wid] = ss;
    __syncthreads();
    if (wid == 0) {
        float v = (lane < 8) ? sred[lane] : 0.f;
#pragma unroll
        for (int o = 4; o > 0; o >>= 1) v += __shfl_xor_sync(0xffffffffu, v, o);
        if (lane == 0) sred[0] = v;
    }
    __syncthreads();
    float r = rsqrtf(sred[0] / (float)ncols + 1e-6f);
    size_t ob = (size_t)row * ldout;
    for (int c = threadIdx.x; c < ncols; c += blockDim.x) {
        bf16 h, l; bsplit(ip[c] * r * w[c], h, l);
        oh[ob + c] = h; ol[ob + c] = l;
    }
}

// ---------------- RoPE ----------------
__device__ __forceinline__ float2 rope_cs(int pos, int i) {
    float freq = powf(10000.0f, -(float)(2 * i) / 64.0f);
    float ang = (float)pos * freq;
    float c, s;
    sincosf(ang, &s, &c);
    return make_float2(c, s);
}

__global__ void rope_k_kernel(const float* __restrict__ ckv_kpe,
                              bf16* __restrict__ kh, bf16* __restrict__ kl) {
    int s = blockIdx.x, j = threadIdx.x;  // 64 threads
    const float* src = ckv_kpe + (size_t)s * 576 + 512;
    float2 cs = rope_cs(s, j & 31);
    float x = src[j];
    float rot = (j < 32) ? -src[j + 32] : src[j - 32];
    bf16 h, l; bsplit(x * cs.x + rot * cs.y, h, l);
    size_t o = (size_t)s * 576 + 512 + j;
    kh[o] = h; kl[o] = l;
}

__global__ void rope_q_kernel(const bf16* __restrict__ qh_in, const bf16* __restrict__ ql_in,
                              bf16* __restrict__ qh, bf16* __restrict__ ql) {
    int s = blockIdx.x, h = blockIdx.y, j = threadIdx.x;  // 64 threads
    size_t base = (size_t)s * 3072 + h * 192 + 128;
    float2 cs = rope_cs(s, j & 31);
    float x = __bfloat162float(qh_in[base + j]) + __bfloat162float(ql_in[base + j]);
    int jr = (j < 32) ? (j + 32) : (j - 32);
    float rv = __bfloat162float(qh_in[base + jr]) + __bfloat162float(ql_in[base + jr]);
    float rot = (j < 32) ? -rv : rv;
    bf16 hh, ll; bsplit(x * cs.x + rot * cs.y, hh, ll);
    size_t o = ((size_t)h * SS + s) * 576 + 512 + j;
    qh[o] = hh; ql[o] = ll;
}

// ---------------- causal softmax: fp32 scores -> hi/lo attn ----------------
__global__ __launch_bounds__(256) void softmax_causal(
    const float* __restrict__ scores, bf16* __restrict__ ah, bf16* __restrict__ al,
    float scale)
{
    int q = blockIdx.x, h = blockIdx.y;
    const float* row = scores + ((size_t)h * SS + q) * SS;
    size_t ob = ((size_t)h * SS + q) * SS;
    int tid = threadIdx.x;
    int n = q + 1;
    int kcap = min(SS, ((q >> 7) + 1) << 7);   // gemm12 reads k < kcap

    float m = -1e30f;
    for (int k = tid; k < n; k += 256) m = fmaxf(m, row[k] * scale);
    __shared__ float sred[32];
#pragma unroll
    for (int o = 16; o > 0; o >>= 1) m = fmaxf(m, __shfl_xor_sync(0xffffffffu, m, o));
    int lane = tid & 31, wid = tid >> 5;
    if (lane == 0) sred[wid] = m;
    __syncthreads();
    if (wid == 0) {
        float v = (lane < 8) ? sred[lane] : -1e30f;
#pragma unroll
        for (int o = 4; o > 0; o >>= 1) v = fmaxf(v, __shfl_xor_sync(0xffffffffu, v, o));
        if (lane == 0) sred[0] = v;
    }
    __syncthreads();
    m = sred[0];

    float ssum = 0.f;
    for (int k = tid; k < n; k += 256) ssum += __expf(row[k] * scale - m);
#pragma unroll
    for (int o = 16; o > 0; o >>= 1) ssum += __shfl_xor_sync(0xffffffffu, ssum, o);
    if (lane == 0) sred[wid] = ssum;
    __syncthreads();
    if (wid == 0) {
        float v = (lane < 8) ? sred[lane] : 0.f;
#pragma unroll
        for (int o = 4; o > 0; o >>= 1) v += __shfl_xor_sync(0xffffffffu, v, o);
        if (lane == 0) sred[0] = v;
    }
    __syncthreads();
    float inv = 1.f / sred[0];
    for (int k = tid; k < n; k += 256) {
        bf16 hh, ll; bsplit(__expf(row[k] * scale - m) * inv, hh, ll);
        ah[ob + k] = hh; al[ob + k] = ll;
    }
    bf16 z = __float2bfloat16(0.f);
    for (int k = n + tid; k < kcap; k += 256) { ah[ob + k] = z; al[ob + k] = z; }
}

// ---------------- launch ----------------
extern "C" void kernel_launch(void* const* d_in, const int* in_sizes, int n_in,
                              void* d_out, int out_size)
{
    const float* x        = (const float*)d_in[0];
    const float* w_q_a    = (const float*)d_in[1];
    const float* q_a_ln_w = (const float*)d_in[2];
    const float* w_q_b    = (const float*)d_in[3];
    const float* w_kv_a   = (const float*)d_in[4];
    const float* kv_a_ln_w= (const float*)d_in[5];
    const float* w_kv_b   = (const float*)d_in[6];
    const float* w_o      = (const float*)d_in[7];
    float* out = (float*)d_out;

    float *p_qa, *p_ckv, *p_scores;
    cudaGetSymbolAddress((void**)&p_qa, g_qa);
    cudaGetSymbolAddress((void**)&p_ckv, g_ckv);
    cudaGetSymbolAddress((void**)&p_scores, g_scores);
    bf16 *xh, *xl, *wqah, *wqal, *qah, *qal, *wqbh, *wqbl, *qh, *ql;
    bf16 *wkvah, *wkval, *kfh, *kfl, *wkvbh, *wkvbl, *woh, *wol;
    bf16 *qfh, *qfl, *wabh, *wabl, *ath, *atl, *och, *ocl;
    cudaGetSymbolAddress((void**)&xh, g_x_h);       cudaGetSymbolAddress((void**)&xl, g_x_l);
    cudaGetSymbolAddress((void**)&wqah, g_wqa_h);   cudaGetSymbolAddress((void**)&wqal, g_wqa_l);
    cudaGetSymbolAddress((void**)&qah, g_qa_h);     cudaGetSymbolAddress((void**)&qal, g_qa_l);
    cudaGetSymbolAddress((void**)&wqbh, g_wqb_h);   cudaGetSymbolAddress((void**)&wqbl, g_wqb_l);
    cudaGetSymbolAddress((void**)&qh, g_q_h);       cudaGetSymbolAddress((void**)&ql, g_q_l);
    cudaGetSymbolAddress((void**)&wkvah, g_wkva_h); cudaGetSymbolAddress((void**)&wkval, g_wkva_l);
    cudaGetSymbolAddress((void**)&kfh, g_kfull_h);  cudaGetSymbolAddress((void**)&kfl, g_kfull_l);
    cudaGetSymbolAddress((void**)&wkvbh, g_wkvb_h); cudaGetSymbolAddress((void**)&wkvbl, g_wkvb_l);
    cudaGetSymbolAddress((void**)&woh, g_wo_h);     cudaGetSymbolAddress((void**)&wol, g_wo_l);
    cudaGetSymbolAddress((void**)&qfh, g_qfull_h);  cudaGetSymbolAddress((void**)&qfl, g_qfull_l);
    cudaGetSymbolAddress((void**)&wabh, g_woabs_h); cudaGetSymbolAddress((void**)&wabl, g_woabs_l);
    cudaGetSymbolAddress((void**)&ath, g_attn_h);   cudaGetSymbolAddress((void**)&atl, g_attn_l);
    cudaGetSymbolAddress((void**)&och, g_octx_h);   cudaGetSymbolAddress((void**)&ocl, g_octx_l);

    // opt-in dynamic smem for all gemm instantiations (idempotent)
    cudaFuncSetAttribute(gemm_bs<false,false,false,false>, cudaFuncAttributeMaxDynamicSharedMemorySize, SMEM_BYTES);
    cudaFuncSetAttribute(gemm_bs<false,false,false,true >, cudaFuncAttributeMaxDynamicSharedMemorySize, SMEM_BYTES);
    cudaFuncSetAttribute(gemm_bs<true ,false,false,true >, cudaFuncAttributeMaxDynamicSharedMemorySize, SMEM_BYTES);
    cudaFuncSetAttribute(gemm_bs<true ,true ,false,false>, cudaFuncAttributeMaxDynamicSharedMemorySize, SMEM_BYTES);
    cudaFuncSetAttribute(gemm_bs<false,false,true ,true >, cudaFuncAttributeMaxDynamicSharedMemorySize, SMEM_BYTES);

    const float sm_scale = rsqrtf((float)(DNN + DRR));

    // 0) split inputs into hi/lo planes
    auto spl = [&](const float* in, bf16* h, bf16* l, int n) {
        int n4 = n >> 2;
        split4_k<<<(n4 + 255) / 256, 256>>>(in, h, l, n4);
    };
    spl(x, xh, xl, SS * EE);
    spl(w_q_a, wqah, wqal, EE * QLRR);
    spl(w_q_b, wqbh, wqbl, QLRR * 3072);
    spl(w_kv_a, wkvah, wkval, EE * 576);
    spl(w_kv_b, wkvbh, wkvbl, RR * 4096);
    spl(w_o, woh, wol, 2048 * 2048);

    // 1) qa_raw = x @ w_q_a   [2048x1536, K=2048] -> fp32
    gemm_bs<false,false,false,false><<<dim3(12, 16, 1), 256, SMEM_BYTES>>>(
        xh, xl, wqah, wqal, p_qa, nullptr, nullptr,
        SS, QLRR, EE, EE, QLRR, QLRR, 0, 0, 0);
    // 2) rmsnorm(qa) -> hi/lo
    rmsnorm_k<<<SS, 256>>>(p_qa, q_a_ln_w, qah, qal, QLRR, QLRR, QLRR);
    // 3) q = qa @ w_q_b [2048x3072, K=1536] -> hi/lo
    gemm_bs<false,false,false,true><<<dim3(24, 16, 1), 256, SMEM_BYTES>>>(
        qah, qal, wqbh, wqbl, nullptr, qh, ql,
        SS, 3072, QLRR, QLRR, 3072, 3072, 0, 0, 0);
    // 4) ckv_kpe = x @ w_kv_a [2048x576, K=2048] -> fp32
    gemm_bs<false,false,false,false><<<dim3(5, 16, 1), 256, SMEM_BYTES>>>(
        xh, xl, wkvah, wkval, p_ckv, nullptr, nullptr,
        SS, 576, EE, EE, 576, 576, 0, 0, 0);
    // 5) kfull[:, :512] = rmsnorm(ckv) -> hi/lo
    rmsnorm_k<<<SS, 256>>>(p_ckv, kv_a_ln_w, kfh, kfl, RR, 576, 576);
    // 6) kfull[:, 512:576] = rope(k_pe)
    rope_k_kernel<<<SS, 64>>>(p_ckv, kfh, kfl);
    // 7) qfull pe section = rope(q_pe)
    rope_q_kernel<<<dim3(SS, HH), 64>>>(qh, ql, qfh, qfl);
    // 8) qfull nope = q_nope @ w_uk^T (batched NT; M=2048 N=512 K=128) -> hi/lo
    gemm_bs<true,false,false,true><<<dim3(4, 16, HH), 256, SMEM_BYTES>>>(
        qh, ql, wkvbh, wkvbl, nullptr, qfh, qfl,
        SS, RR, DNN, 3072, 4096, 576, 192LL, 256LL, (long long)SS * 576);
    // 9) w_o_abs[h] = w_uv[h]^T @ w_o[h] (batched NN; M=512 N=2048 K=128) -> hi/lo
    gemm_bs<false,false,false,true><<<dim3(16, 4, HH), 256, SMEM_BYTES>>>(
        wkvbh + 128, wkvbl + 128, woh, wol, nullptr, wabh, wabl,
        RR, EE, DNN, 4096, EE, EE, 256LL, (long long)DNN * EE, (long long)RR * EE);
    // 10) scores[h] = qfull[h] @ kfull^T (batched NT, causal-skip) -> fp32
    gemm_bs<true,true,false,false><<<dim3(16, 16, HH), 256, SMEM_BYTES>>>(
        qfh, qfl, kfh, kfl, p_scores, nullptr, nullptr,
        SS, SS, 576, 576, 576, SS, (long long)SS * 576, 0LL, (long long)SS * SS);
    // 11) softmax -> attn hi/lo (+ zero tail to tile boundary)
    softmax_causal<<<dim3(SS, HH), 256>>>(p_scores, ath, atl, sm_scale);
    // 12) octx = attn[h] @ ckv (batched NN, causal K-limit; M=2048 N=512 K=2048) -> hi/lo
    gemm_bs<false,false,true,true><<<dim3(4, 16, HH), 256, SMEM_BYTES>>>(
        ath, atl, kfh, kfl, nullptr, och, ocl,
        SS, RR, SS, SS, 576, HH * RR, (long long)SS * SS, 0LL, (long long)RR);
    // 13) y = octx @ w_o_abs (NN; M=2048 N=2048 K=8192) -> fp32
    gemm_bs<false,false,false,false><<<dim3(16, 16, 1), 256, SMEM_BYTES>>>(
        och, ocl, wabh, wabl, out, nullptr, nullptr,
        SS, EE, HH * RR, HH * RR, EE, EE, 0, 0, 0);
}

// round 9
// speedup vs baseline: 2.2417x; 1.0662x over previous
#include <cuda_runtime.h>
#include <cuda_bf16.h>
#include <mma.h>
#include <math.h>

using namespace nvcuda;
typedef __nv_bfloat16 bf16;

#define SS 2048
#define EE 2048
#define HH 16
#define DNN 128
#define DRR 64
#define RR 512
#define QLRR 1536

// ---------------- fp32 scratch ----------------
__device__ float g_qa[SS * QLRR];
__device__ float g_ckv[SS * (RR + DRR)];
__device__ float g_scores[(size_t)HH * SS * SS];

// ---------------- bf16 hi/lo planes ----------------
__device__ bf16 g_x_h[SS * EE],          g_x_l[SS * EE];
__device__ bf16 g_wqa_h[EE * QLRR],      g_wqa_l[EE * QLRR];
__device__ bf16 g_qa_h[SS * QLRR],       g_qa_l[SS * QLRR];
__device__ bf16 g_wqb_h[QLRR * 3072],    g_wqb_l[QLRR * 3072];
__device__ bf16 g_q_h[SS * 3072],        g_q_l[SS * 3072];
__device__ bf16 g_wkva_h[EE * 576],      g_wkva_l[EE * 576];
__device__ bf16 g_kfull_h[SS * 576],     g_kfull_l[SS * 576];
__device__ bf16 g_wkvb_h[RR * 4096],     g_wkvb_l[RR * 4096];
__device__ bf16 g_wo_h[2048 * 2048],     g_wo_l[2048 * 2048];
__device__ bf16 g_qfull_h[HH * SS * 576], g_qfull_l[HH * SS * 576];
__device__ bf16 g_woabs_h[HH * RR * EE],  g_woabs_l[HH * RR * EE];
__device__ bf16 g_attn_h[(size_t)HH * SS * SS], g_attn_l[(size_t)HH * SS * SS];
__device__ bf16 g_octx_h[SS * HH * RR],   g_octx_l[SS * HH * RR];

__device__ __forceinline__ void bsplit(float v, bf16& h, bf16& l) {
    h = __float2bfloat16(v);
    l = __float2bfloat16(v - __bfloat162float(h));
}

// ---------------- cp.async helpers ----------------
__device__ __forceinline__ void cpa16(void* sdst, const void* gsrc, bool pred) {
    unsigned s = (unsigned)__cvta_generic_to_shared(sdst);
    int sz = pred ? 16 : 0;
    asm volatile("cp.async.cg.shared.global [%0], [%1], 16, %2;\n"
                 :: "r"(s), "l"(gsrc), "r"(sz));
}
__device__ __forceinline__ void cp_commit() { asm volatile("cp.async.commit_group;\n"); }
__device__ __forceinline__ void cp_wait1()  { asm volatile("cp.async.wait_group 1;\n" ::: "memory"); }

// ---------------- bf16-split GEMM with cp.async pipeline ----------------
// Inputs are pre-split hi/lo bf16 planes. acc += Ah*Bh + Ah*Bl + Al*Bh (fp32 acc).
// BM=BN=128, BK=32, 256 thr = 8 warps (4x2), warp tile 32x64 (2x4 m16n16k16).
// 2-stage cp.async double buffering. __launch_bounds__(256, 2) caps regs at 128
// so TWO CTAs co-reside per SM (regfile 64K): barrier/cp-wait bubbles of one CTA
// are filled by the other's MMA issue.
// TRANSB: B planes are [N][K] k-contig, consumed via col_major fragments.
// OUTSPLIT: write hi/lo bf16 planes via smem roundtrip; else fp32 C.
// Reqs: M%128==0, K%32==0, N%8==0, strides %8==0.
#define ALD2 40     // k-stride for A / NT-B smem rows (elems)
#define BLD2 136    // n-stride for NN-B smem rows (elems)
#define PLANE 5120  // max plane elems per stage (128*40)
#define SMEM_BYTES (2 * 4 * PLANE * 2)   // 81920

extern __shared__ bf16 dsm[];

template <bool TRANSB, bool CSKIP, bool CKLIM, bool OUTSPLIT>
__global__ __launch_bounds__(256, 2) void gemm_bs(
    const bf16* __restrict__ Ah, const bf16* __restrict__ Al,
    const bf16* __restrict__ Bh, const bf16* __restrict__ Bl,
    float* __restrict__ C, bf16* __restrict__ Ch, bf16* __restrict__ Cl,
    int M, int N, int K, int lda, int ldb, int ldc,
    long long sA, long long sB, long long sC)
{
    int bz = blockIdx.z;
    Ah += sA * bz; Al += sA * bz; Bh += sB * bz; Bl += sB * bz;
    if (OUTSPLIT) { Ch += sC * bz; Cl += sC * bz; } else { C += sC * bz; }
    int bx = blockIdx.x, by = blockIdx.y;
    if (CSKIP && bx > by) return;
    int kEnd = CKLIM ? min(K, (by + 1) * 128) : K;   // multiple of 32

    int tid = threadIdx.x;
    int wid = tid >> 5;
    int wr = wid >> 1;   // 0..3
    int wc = wid & 1;    // 0..1

    wmma::fragment<wmma::accumulator, 16, 16, 16, float> acc[2][4];
#pragma unroll
    for (int i = 0; i < 2; i++)
#pragma unroll
        for (int j = 0; j < 4; j++) wmma::fill_fragment(acc[i][j], 0.0f);

    auto ldg = [&](int it, int st) {
        int k0 = it << 5;
        bf16* base = dsm + st * 4 * PLANE;
        bf16* sAh = base;         bf16* sAl = base + PLANE;
        bf16* sBh = base + 2 * PLANE; bf16* sBl = base + 3 * PLANE;
#pragma unroll
        for (int r = 0; r < 2; r++) {
            int c = tid * 2 + r;            // 0..511
            int row = c >> 2, kc = (c & 3) << 3;
            size_t go = (size_t)(by * 128 + row) * lda + k0 + kc;
            cpa16(sAh + row * ALD2 + kc, Ah + go, true);
            cpa16(sAl + row * ALD2 + kc, Al + go, true);
        }
        if (!TRANSB) {
#pragma unroll
            for (int r = 0; r < 2; r++) {
                int c = tid * 2 + r;
                int row = c >> 4, nc = (c & 15) << 3;
                int gn = bx * 128 + nc;
                bool p = gn < N;
                size_t go = p ? ((size_t)(k0 + row) * ldb + gn) : 0;
                cpa16(sBh + row * BLD2 + nc, Bh + go, p);
                cpa16(sBl + row * BLD2 + nc, Bl + go, p);
            }
        } else {
#pragma unroll
            for (int r = 0; r < 2; r++) {
                int c = tid * 2 + r;
                int row = c >> 2, kc = (c & 3) << 3;
                int gn = bx * 128 + row;
                bool p = gn < N;
                size_t go = p ? ((size_t)gn * ldb + k0 + kc) : 0;
                cpa16(sBh + row * ALD2 + kc, Bh + go, p);
                cpa16(sBl + row * ALD2 + kc, Bl + go, p);
            }
        }
    };

    int nIter = kEnd >> 5;
    ldg(0, 0); cp_commit();
    if (nIter > 1) ldg(1, 1);
    cp_commit();
    cp_wait1(); __syncthreads();

    for (int it = 0; it < nIter; it++) {
        int st = it & 1;
        bf16* base = dsm + st * 4 * PLANE;
        bf16* sAh = base;             bf16* sAl = base + PLANE;
        bf16* sBh = base + 2 * PLANE; bf16* sBl = base + 3 * PLANE;

#pragma unroll
        for (int kc = 0; kc < 32; kc += 16) {
            wmma::fragment<wmma::matrix_a, 16, 16, 16, bf16, wmma::row_major> ah[2], al[2];
#pragma unroll
            for (int i = 0; i < 2; i++) {
                int m0 = (wr * 32 + i * 16) * ALD2 + kc;
                wmma::load_matrix_sync(ah[i], sAh + m0, ALD2);
                wmma::load_matrix_sync(al[i], sAl + m0, ALD2);
            }
            if (!TRANSB) {
                wmma::fragment<wmma::matrix_b, 16, 16, 16, bf16, wmma::row_major> bh[4], bl[4];
#pragma unroll
                for (int j = 0; j < 4; j++) {
                    int n0 = kc * BLD2 + wc * 64 + j * 16;
                    wmma::load_matrix_sync(bh[j], sBh + n0, BLD2);
                    wmma::load_matrix_sync(bl[j], sBl + n0, BLD2);
                }
#pragma unroll
                for (int i = 0; i < 2; i++)
#pragma unroll
                    for (int j = 0; j < 4; j++) {
                        wmma::mma_sync(acc[i][j], ah[i], bh[j], acc[i][j]);
                        wmma::mma_sync(acc[i][j], ah[i], bl[j], acc[i][j]);
                        wmma::mma_sync(acc[i][j], al[i], bh[j], acc[i][j]);
                    }
            } else {
                wmma::fragment<wmma::matrix_b, 16, 16, 16, bf16, wmma::col_major> bh[4], bl[4];
#pragma unroll
                for (int j = 0; j < 4; j++) {
                    int n0 = (wc * 64 + j * 16) * ALD2 + kc;
                    wmma::load_matrix_sync(bh[j], sBh + n0, ALD2);
                    wmma::load_matrix_sync(bl[j], sBl + n0, ALD2);
                }
#pragma unroll
                for (int i = 0; i < 2; i++)
#pragma unroll
                    for (int j = 0; j < 4; j++) {
                        wmma::mma_sync(acc[i][j], ah[i], bh[j], acc[i][j]);
                        wmma::mma_sync(acc[i][j], ah[i], bl[j], acc[i][j]);
                        wmma::mma_sync(acc[i][j], al[i], bh[j], acc[i][j]);
                    }
            }
        }

        __syncthreads();
        if (it + 2 < nIter) ldg(it + 2, st);
        cp_commit();
        cp_wait1(); __syncthreads();
    }

    if (!OUTSPLIT) {
#pragma unroll
        for (int i = 0; i < 2; i++) {
            int m0 = by * 128 + wr * 32 + i * 16;
#pragma unroll
            for (int j = 0; j < 4; j++) {
                int n0 = bx * 128 + wc * 64 + j * 16;
                if (n0 < N)
                    wmma::store_matrix_sync(C + (size_t)m0 * ldc + n0, acc[i][j], ldc,
                                            wmma::mem_row_major);
            }
        }
    } else {
        float* sC = reinterpret_cast<float*>(dsm);
        __syncthreads();
#pragma unroll
        for (int i = 0; i < 2; i++)
#pragma unroll
            for (int j = 0; j < 4; j++)
                wmma::store_matrix_sync(&sC[(wr * 32 + i * 16) * 128 + wc * 64 + j * 16],
                                        acc[i][j], 128, wmma::mem_row_major);
        __syncthreads();
        int row = tid >> 1;
        int colbase = (tid & 1) << 6;
        size_t rbase = (size_t)(by * 128 + row) * ldc;
#pragma unroll
        for (int v = 0; v < 16; v++) {
            int cc = colbase + v * 4;
            int gn = bx * 128 + cc;
            if (gn < N) {
                float4 f = *reinterpret_cast<const float4*>(&sC[row * 128 + cc]);
                bf16 h[4], l[4];
                bsplit(f.x, h[0], l[0]); bsplit(f.y, h[1], l[1]);
                bsplit(f.z, h[2], l[2]); bsplit(f.w, h[3], l[3]);
                *reinterpret_cast<uint2*>(Ch + rbase + gn) = *reinterpret_cast<uint2*>(h);
                *reinterpret_cast<uint2*>(Cl + rbase + gn) = *reinterpret_cast<uint2*>(l);
            }
        }
    }
}

// ---------------- fp32 -> hi/lo split (vectorized) ----------------
__global__ __launch_bounds__(256) void split4_k(
    const float* __restrict__ in, bf16* __restrict__ h, bf16* __restrict__ l, int n4)
{
    int i = blockIdx.x * 256 + threadIdx.x;
    if (i < n4) {
        float4 f = reinterpret_cast<const float4*>(in)[i];
        bf16 hh[4], ll[4];
        bsplit(f.x, hh[0], ll[0]); bsplit(f.y, hh[1], ll[1]);
        bsplit(f.z, hh[2], ll[2]); bsplit(f.w, hh[3], ll[3]);
        reinterpret_cast<uint2*>(h)[i] = *reinterpret_cast<uint2*>(hh);
        reinterpret_cast<uint2*>(l)[i] = *reinterpret_cast<uint2*>(ll);
    }
}

// ---------------- rmsnorm: fp32 in -> hi/lo bf16 out ----------------
__global__ __launch_bounds__(256) void rmsnorm_k(
    const float* __restrict__ in, const float* __restrict__ w,
    bf16* __restrict__ oh, bf16* __restrict__ ol,
    int ncols, int ldin, int ldout)
{
    int row = blockIdx.x;
    const float* ip = in + (size_t)row * ldin;
    float ss = 0.f;
    for (int c = threadIdx.x; c < ncols; c += blockDim.x) {
        float v = ip[c];
        ss += v * v;
    }
    __shared__ float sred[32];
#pragma unroll
    for (int o = 16; o > 0; o >>= 1) ss += __shfl_xor_sync(0xffffffffu, ss, o);
    int lane = threadIdx.x & 31, wid = threadIdx.x >> 5;
    if (lane == 0) sred[wid] = ss;
    __syncthreads();
    if (wid == 0) {
        float v = (lane < 8) ? sred[lane] : 0.f;
#pragma unroll
        for (int o = 4; o > 0; o >>= 1) v += __shfl_xor_sync(0xffffffffu, v, o);
        if (lane == 0) sred[0] = v;
    }
    __syncthreads();
    float r = rsqrtf(sred[0] / (float)ncols + 1e-6f);
    size_t ob = (size_t)row * ldout;
    for (int c = threadIdx.x; c < ncols; c += blockDim.x) {
        bf16 h, l; bsplit(ip[c] * r * w[c], h, l);
        oh[ob + c] = h; ol[ob + c] = l;
    }
}

// ---------------- RoPE ----------------
__device__ __forceinline__ float2 rope_cs(int pos, int i) {
    float freq = powf(10000.0f, -(float)(2 * i) / 64.0f);
    float ang = (float)pos * freq;
    float c, s;
    sincosf(ang, &s, &c);
    return make_float2(c, s);
}

__global__ void rope_k_kernel(const float* __restrict__ ckv_kpe,
                              bf16* __restrict__ kh, bf16* __restrict__ kl) {
    int s = blockIdx.x, j = threadIdx.x;  // 64 threads
    const float* src = ckv_kpe + (size_t)s * 576 + 512;
    float2 cs = rope_cs(s, j & 31);
    float x = src[j];
    float rot = (j < 32) ? -src[j + 32] : src[j - 32];
    bf16 h, l; bsplit(x * cs.x + rot * cs.y, h, l);
    size_t o = (size_t)s * 576 + 512 + j;
    kh[o] = h; kl[o] = l;
}

__global__ void rope_q_kernel(const bf16* __restrict__ qh_in, const bf16* __restrict__ ql_in,
                              bf16* __restrict__ qh, bf16* __restrict__ ql) {
    int s = blockIdx.x, h = blockIdx.y, j = threadIdx.x;  // 64 threads
    size_t base = (size_t)s * 3072 + h * 192 + 128;
    float2 cs = rope_cs(s, j & 31);
    float x = __bfloat162float(qh_in[base + j]) + __bfloat162float(ql_in[base + j]);
    int jr = (j < 32) ? (j + 32) : (j - 32);
    float rv = __bfloat162float(qh_in[base + jr]) + __bfloat162float(ql_in[base + jr]);
    float rot = (j < 32) ? -rv : rv;
    bf16 hh, ll; bsplit(x * cs.x + rot * cs.y, hh, ll);
    size_t o = ((size_t)h * SS + s) * 576 + 512 + j;
    qh[o] = hh; ql[o] = ll;
}

// ---------------- causal softmax: fp32 scores -> hi/lo attn ----------------
__global__ __launch_bounds__(256) void softmax_causal(
    const float* __restrict__ scores, bf16* __restrict__ ah, bf16* __restrict__ al,
    float scale)
{
    int q = blockIdx.x, h = blockIdx.y;
    const float* row = scores + ((size_t)h * SS + q) * SS;
    size_t ob = ((size_t)h * SS + q) * SS;
    int tid = threadIdx.x;
    int n = q + 1;
    int kcap = min(SS, ((q >> 7) + 1) << 7);   // gemm12 reads k < kcap

    float m = -1e30f;
    for (int k = tid; k < n; k += 256) m = fmaxf(m, row[k] * scale);
    __shared__ float sred[32];
#pragma unroll
    for (int o = 16; o > 0; o >>= 1) m = fmaxf(m, __shfl_xor_sync(0xffffffffu, m, o));
    int lane = tid & 31, wid = tid >> 5;
    if (lane == 0) sred[wid] = m;
    __syncthreads();
    if (wid == 0) {
        float v = (lane < 8) ? sred[lane] : -1e30f;
#pragma unroll
        for (int o = 4; o > 0; o >>= 1) v = fmaxf(v, __shfl_xor_sync(0xffffffffu, v, o));
        if (lane == 0) sred[0] = v;
    }
    __syncthreads();
    m = sred[0];

    float ssum = 0.f;
    for (int k = tid; k < n; k += 256) ssum += __expf(row[k] * scale - m);
#pragma unroll
    for (int o = 16; o > 0; o >>= 1) ssum += __shfl_xor_sync(0xffffffffu, ssum, o);
    if (lane == 0) sred[wid] = ssum;
    __syncthreads();
    if (wid == 0) {
        float v = (lane < 8) ? sred[lane] : 0.f;
#pragma unroll
        for (int o = 4; o > 0; o >>= 1) v += __shfl_xor_sync(0xffffffffu, v, o);
        if (lane == 0) sred[0] = v;
    }
    __syncthreads();
    float inv = 1.f / sred[0];
    for (int k = tid; k < n; k += 256) {
        bf16 hh, ll; bsplit(__expf(row[k] * scale - m) * inv, hh, ll);
        ah[ob + k] = hh; al[ob + k] = ll;
    }
    bf16 z = __float2bfloat16(0.f);
    for (int k = n + tid; k < kcap; k += 256) { ah[ob + k] = z; al[ob + k] = z; }
}

// ---------------- launch ----------------
extern "C" void kernel_launch(void* const* d_in, const int* in_sizes, int n_in,
                              void* d_out, int out_size)
{
    const float* x        = (const float*)d_in[0];
    const float* w_q_a    = (const float*)d_in[1];
    const float* q_a_ln_w = (const float*)d_in[2];
    const float* w_q_b    = (const float*)d_in[3];
    const float* w_kv_a   = (const float*)d_in[4];
    const float* kv_a_ln_w= (const float*)d_in[5];
    const float* w_kv_b   = (const float*)d_in[6];
    const float* w_o      = (const float*)d_in[7];
    float* out = (float*)d_out;

    float *p_qa, *p_ckv, *p_scores;
    cudaGetSymbolAddress((void**)&p_qa, g_qa);
    cudaGetSymbolAddress((void**)&p_ckv, g_ckv);
    cudaGetSymbolAddress((void**)&p_scores, g_scores);
    bf16 *xh, *xl, *wqah, *wqal, *qah, *qal, *wqbh, *wqbl, *qh, *ql;
    bf16 *wkvah, *wkval, *kfh, *kfl, *wkvbh, *wkvbl, *woh, *wol;
    bf16 *qfh, *qfl, *wabh, *wabl, *ath, *atl, *och, *ocl;
    cudaGetSymbolAddress((void**)&xh, g_x_h);       cudaGetSymbolAddress((void**)&xl, g_x_l);
    cudaGetSymbolAddress((void**)&wqah, g_wqa_h);   cudaGetSymbolAddress((void**)&wqal, g_wqa_l);
    cudaGetSymbolAddress((void**)&qah, g_qa_h);     cudaGetSymbolAddress((void**)&qal, g_qa_l);
    cudaGetSymbolAddress((void**)&wqbh, g_wqb_h);   cudaGetSymbolAddress((void**)&wqbl, g_wqb_l);
    cudaGetSymbolAddress((void**)&qh, g_q_h);       cudaGetSymbolAddress((void**)&ql, g_q_l);
    cudaGetSymbolAddress((void**)&wkvah, g_wkva_h); cudaGetSymbolAddress((void**)&wkval, g_wkva_l);
    cudaGetSymbolAddress((void**)&kfh, g_kfull_h);  cudaGetSymbolAddress((void**)&kfl, g_kfull_l);
    cudaGetSymbolAddress((void**)&wkvbh, g_wkvb_h); cudaGetSymbolAddress((void**)&wkvbl, g_wkvb_l);
    cudaGetSymbolAddress((void**)&woh, g_wo_h);     cudaGetSymbolAddress((void**)&wol, g_wo_l);
    cudaGetSymbolAddress((void**)&qfh, g_qfull_h);  cudaGetSymbolAddress((void**)&qfl, g_qfull_l);
    cudaGetSymbolAddress((void**)&wabh, g_woabs_h); cudaGetSymbolAddress((void**)&wabl, g_woabs_l);
    cudaGetSymbolAddress((void**)&ath, g_attn_h);   cudaGetSymbolAddress((void**)&atl, g_attn_l);
    cudaGetSymbolAddress((void**)&och, g_octx_h);   cudaGetSymbolAddress((void**)&ocl, g_octx_l);

    // opt-in dynamic smem for all gemm instantiations (idempotent)
    cudaFuncSetAttribute(gemm_bs<false,false,false,false>, cudaFuncAttributeMaxDynamicSharedMemorySize, SMEM_BYTES);
    cudaFuncSetAttribute(gemm_bs<false,false,false,true >, cudaFuncAttributeMaxDynamicSharedMemorySize, SMEM_BYTES);
    cudaFuncSetAttribute(gemm_bs<true ,false,false,true >, cudaFuncAttributeMaxDynamicSharedMemorySize, SMEM_BYTES);
    cudaFuncSetAttribute(gemm_bs<true ,true ,false,false>, cudaFuncAttributeMaxDynamicSharedMemorySize, SMEM_BYTES);
    cudaFuncSetAttribute(gemm_bs<false,false,true ,true >, cudaFuncAttributeMaxDynamicSharedMemorySize, SMEM_BYTES);

    const float sm_scale = rsqrtf((float)(DNN + DRR));

    // 0) split inputs into hi/lo planes
    auto spl = [&](const float* in, bf16* h, bf16* l, int n) {
        int n4 = n >> 2;
        split4_k<<<(n4 + 255) / 256, 256>>>(in, h, l, n4);
    };
    spl(x, xh, xl, SS * EE);
    spl(w_q_a, wqah, wqal, EE * QLRR);
    spl(w_q_b, wqbh, wqbl, QLRR * 3072);
    spl(w_kv_a, wkvah, wkval, EE * 576);
    spl(w_kv_b, wkvbh, wkvbl, RR * 4096);
    spl(w_o, woh, wol, 2048 * 2048);

    // 1) qa_raw = x @ w_q_a   [2048x1536, K=2048] -> fp32
    gemm_bs<false,false,false,false><<<dim3(12, 16, 1), 256, SMEM_BYTES>>>(
        xh, xl, wqah, wqal, p_qa, nullptr, nullptr,
        SS, QLRR, EE, EE, QLRR, QLRR, 0, 0, 0);
    // 2) rmsnorm(qa) -> hi/lo
    rmsnorm_k<<<SS, 256>>>(p_qa, q_a_ln_w, qah, qal, QLRR, QLRR, QLRR);
    // 3) q = qa @ w_q_b [2048x3072, K=1536] -> hi/lo
    gemm_bs<false,false,false,true><<<dim3(24, 16, 1), 256, SMEM_BYTES>>>(
        qah, qal, wqbh, wqbl, nullptr, qh, ql,
        SS, 3072, QLRR, QLRR, 3072, 3072, 0, 0, 0);
    // 4) ckv_kpe = x @ w_kv_a [2048x576, K=2048] -> fp32
    gemm_bs<false,false,false,false><<<dim3(5, 16, 1), 256, SMEM_BYTES>>>(
        xh, xl, wkvah, wkval, p_ckv, nullptr, nullptr,
        SS, 576, EE, EE, 576, 576, 0, 0, 0);
    // 5) kfull[:, :512] = rmsnorm(ckv) -> hi/lo
    rmsnorm_k<<<SS, 256>>>(p_ckv, kv_a_ln_w, kfh, kfl, RR, 576, 576);
    // 6) kfull[:, 512:576] = rope(k_pe)
    rope_k_kernel<<<SS, 64>>>(p_ckv, kfh, kfl);
    // 7) qfull pe section = rope(q_pe)
    rope_q_kernel<<<dim3(SS, HH), 64>>>(qh, ql, qfh, qfl);
    // 8) qfull nope = q_nope @ w_uk^T (batched NT; M=2048 N=512 K=128) -> hi/lo
    gemm_bs<true,false,false,true><<<dim3(4, 16, HH), 256, SMEM_BYTES>>>(
        qh, ql, wkvbh, wkvbl, nullptr, qfh, qfl,
        SS, RR, DNN, 3072, 4096, 576, 192LL, 256LL, (long long)SS * 576);
    // 9) w_o_abs[h] = w_uv[h]^T @ w_o[h] (batched NN; M=512 N=2048 K=128) -> hi/lo
    gemm_bs<false,false,false,true><<<dim3(16, 4, HH), 256, SMEM_BYTES>>>(
        wkvbh + 128, wkvbl + 128, woh, wol, nullptr, wabh, wabl,
        RR, EE, DNN, 4096, EE, EE, 256LL, (long long)DNN * EE, (long long)RR * EE);
    // 10) scores[h] = qfull[h] @ kfull^T (batched NT, causal-skip) -> fp32
    gemm_bs<true,true,false,false><<<dim3(16, 16, HH), 256, SMEM_BYTES>>>(
        qfh, qfl, kfh, kfl, p_scores, nullptr, nullptr,
        SS, SS, 576, 576, 576, SS, (long long)SS * 576, 0LL, (long long)SS * SS);
    // 11) softmax -> attn hi/lo (+ zero tail to tile boundary)
    softmax_causal<<<dim3(SS, HH), 256>>>(p_scores, ath, atl, sm_scale);
    // 12) octx = attn[h] @ ckv (batched NN, causal K-limit; M=2048 N=512 K=2048) -> hi/lo
    gemm_bs<false,false,true,true><<<dim3(4, 16, HH), 256, SMEM_BYTES>>>(
        ath, atl, kfh, kfl, nullptr, och, ocl,
        SS, RR, SS, SS, 576, HH * RR, (long long)SS * SS, 0LL, (long long)RR);
    // 13) y = octx @ w_o_abs (NN; M=2048 N=2048 K=8192) -> fp32
    gemm_bs<false,false,false,false><<<dim3(16, 16, 1), 256, SMEM_BYTES>>>(
        och, ocl, wabh, wabl, out, nullptr, nullptr,
        SS, EE, HH * RR, HH * RR, EE, EE, 0, 0, 0);
}

// round 15
// speedup vs baseline: 2.3122x; 1.0315x over previous
#include <cuda_runtime.h>
#include <cuda_bf16.h>
#include <mma.h>
#include <math.h>

using namespace nvcuda;
typedef __nv_bfloat16 bf16;

#define SS 2048
#define EE 2048
#define HH 16
#define DNN 128
#define DRR 64
#define RR 512
#define QLRR 1536

// ---------------- fp32 scratch ----------------
__device__ float g_qa[SS * QLRR];
__device__ float g_ckv[SS * (RR + DRR)];
__device__ float g_scores[(size_t)HH * SS * SS];

// ---------------- bf16 hi/lo planes ----------------
__device__ bf16 g_x_h[SS * EE],          g_x_l[SS * EE];
__device__ bf16 g_wqa_h[EE * QLRR],      g_wqa_l[EE * QLRR];
__device__ bf16 g_qa_h[SS * QLRR],       g_qa_l[SS * QLRR];
__device__ bf16 g_wqb_h[QLRR * 3072],    g_wqb_l[QLRR * 3072];
__device__ bf16 g_q_h[SS * 3072],        g_q_l[SS * 3072];
__device__ bf16 g_wkva_h[EE * 576],      g_wkva_l[EE * 576];
__device__ bf16 g_kfull_h[SS * 576],     g_kfull_l[SS * 576];
__device__ bf16 g_wkvb_h[RR * 4096],     g_wkvb_l[RR * 4096];
__device__ bf16 g_wo_h[2048 * 2048],     g_wo_l[2048 * 2048];
__device__ bf16 g_qfull_h[HH * SS * 576], g_qfull_l[HH * SS * 576];
__device__ bf16 g_woabs_h[HH * RR * EE],  g_woabs_l[HH * RR * EE];
__device__ bf16 g_attn_h[(size_t)HH * SS * SS], g_attn_l[(size_t)HH * SS * SS];
__device__ bf16 g_octx_h[SS * HH * RR],   g_octx_l[SS * HH * RR];

__device__ __forceinline__ void bsplit(float v, bf16& h, bf16& l) {
    h = __float2bfloat16(v);
    l = __float2bfloat16(v - __bfloat162float(h));
}

// ---------------- cp.async helpers ----------------
__device__ __forceinline__ void cpa16(void* sdst, const void* gsrc, bool pred) {
    unsigned s = (unsigned)__cvta_generic_to_shared(sdst);
    int sz = pred ? 16 : 0;
    asm volatile("cp.async.cg.shared.global [%0], [%1], 16, %2;\n"
                 :: "r"(s), "l"(gsrc), "r"(sz));
}
__device__ __forceinline__ void cp_commit() { asm volatile("cp.async.commit_group;\n"); }
__device__ __forceinline__ void cp_wait1()  { asm volatile("cp.async.wait_group 1;\n" ::: "memory"); }

// ---------------- bf16-split GEMM, 3-stage cp.async pipeline ----------------
// Inputs pre-split hi/lo bf16 planes; acc += Ah*Bh + Ah*Bl + Al*Bh (fp32 acc).
// BM=BN=128, BK=32, 256 thr = 8 warps (4x2), warp tile 32x64 (2x4 m16n16k16).
// 3-stage buffers -> ONE __syncthreads() per iteration. Term-outer MMA order:
// 8 independent accumulators between reuses.
// STAGE GEOMETRY IS TEMPLATE-DEPENDENT (R11 crash fix): TRANSB stores B with
// the A layout (128 rows x ALD2), so its B plane slot must be PLANE_A, not
// the 32x136 NN size. NN: stage 37888B (2 CTAs/SM). TRANSB: 40960B (1 CTA/SM,
// smem-limited; those gemms have thousands of blocks).
// TRANSB: B planes [N][K] k-contig via col_major frags. OUTSPLIT: hi/lo out.
// Reqs: M%128==0, K%32==0, N%8==0, strides %8==0.
#define ALD2 40       // A / NT-B smem k-stride (elems)
#define BLD2 136      // NN-B smem n-stride (elems)
#define PLANE_A 5120  // 128*40
#define PLANE_BN 4352 // 32*136

#define SMEM_NN (3 * (2 * PLANE_A + 2 * PLANE_BN) * 2)  // 113664
#define SMEM_NT (3 * (4 * PLANE_A) * 2)                 // 122880

extern __shared__ bf16 dsm[];

template <bool TRANSB, bool CSKIP, bool CKLIM, bool OUTSPLIT>
__global__ __launch_bounds__(256, 2) void gemm_bs(
    const bf16* __restrict__ Ah, const bf16* __restrict__ Al,
    const bf16* __restrict__ Bh, const bf16* __restrict__ Bl,
    float* __restrict__ C, bf16* __restrict__ Ch, bf16* __restrict__ Cl,
    int M, int N, int K, int lda, int ldb, int ldc,
    long long sA, long long sB, long long sC)
{
    constexpr int PB = TRANSB ? PLANE_A : PLANE_BN;        // B plane slot size
    constexpr int STAGE_E = 2 * PLANE_A + 2 * PB;          // elems per stage

    int bz = blockIdx.z;
    Ah += sA * bz; Al += sA * bz; Bh += sB * bz; Bl += sB * bz;
    if (OUTSPLIT) { Ch += sC * bz; Cl += sC * bz; } else { C += sC * bz; }
    int bx = blockIdx.x, by = blockIdx.y;
    if (CSKIP && bx > by) return;
    int kEnd = CKLIM ? min(K, (by + 1) * 128) : K;   // multiple of 32

    int tid = threadIdx.x;
    int wid = tid >> 5;
    int wr = wid >> 1;   // 0..3
    int wc = wid & 1;    // 0..1

    wmma::fragment<wmma::accumulator, 16, 16, 16, float> acc[2][4];
#pragma unroll
    for (int i = 0; i < 2; i++)
#pragma unroll
        for (int j = 0; j < 4; j++) wmma::fill_fragment(acc[i][j], 0.0f);

    auto ldg = [&](int it, int st) {
        int k0 = it << 5;
        bf16* base = dsm + st * STAGE_E;
        bf16* sAh = base;                 bf16* sAl = base + PLANE_A;
        bf16* sBh = base + 2 * PLANE_A;   bf16* sBl = base + 2 * PLANE_A + PB;
#pragma unroll
        for (int r = 0; r < 2; r++) {
            int c = tid * 2 + r;            // 0..511 granules (16B)
            int row = c >> 2, kc = (c & 3) << 3;
            size_t go = (size_t)(by * 128 + row) * lda + k0 + kc;
            cpa16(sAh + row * ALD2 + kc, Ah + go, true);
            cpa16(sAl + row * ALD2 + kc, Al + go, true);
        }
        if (!TRANSB) {
#pragma unroll
            for (int r = 0; r < 2; r++) {
                int c = tid * 2 + r;
                int row = c >> 4, nc = (c & 15) << 3;   // 32 rows x 128 cols
                int gn = bx * 128 + nc;
                bool p = gn < N;
                size_t go = p ? ((size_t)(k0 + row) * ldb + gn) : 0;
                cpa16(sBh + row * BLD2 + nc, Bh + go, p);
                cpa16(sBl + row * BLD2 + nc, Bl + go, p);
            }
        } else {
#pragma unroll
            for (int r = 0; r < 2; r++) {
                int c = tid * 2 + r;
                int row = c >> 2, kc = (c & 3) << 3;    // 128 rows x 32 k
                int gn = bx * 128 + row;
                bool p = gn < N;
                size_t go = p ? ((size_t)gn * ldb + k0 + kc) : 0;
                cpa16(sBh + row * ALD2 + kc, Bh + go, p);
                cpa16(sBl + row * ALD2 + kc, Bl + go, p);
            }
        }
    };

    int nIter = kEnd >> 5;
    ldg(0, 0); cp_commit();
    if (nIter > 1) ldg(1, 1);
    cp_commit();

    for (int it = 0; it < nIter; it++) {
        int st = it % 3;
        cp_wait1();            // group `it` complete (<=1 group outstanding)
        __syncthreads();       // single barrier per iteration

        bf16* base = dsm + st * STAGE_E;
        bf16* sAh = base;                 bf16* sAl = base + PLANE_A;
        bf16* sBh = base + 2 * PLANE_A;   bf16* sBl = base + 2 * PLANE_A + PB;

#pragma unroll
        for (int kc = 0; kc < 32; kc += 16) {
            wmma::fragment<wmma::matrix_a, 16, 16, 16, bf16, wmma::row_major> ah[2], al[2];
#pragma unroll
            for (int i = 0; i < 2; i++) {
                int m0 = (wr * 32 + i * 16) * ALD2 + kc;
                wmma::load_matrix_sync(ah[i], sAh + m0, ALD2);
                wmma::load_matrix_sync(al[i], sAl + m0, ALD2);
            }
            if (!TRANSB) {
                wmma::fragment<wmma::matrix_b, 16, 16, 16, bf16, wmma::row_major> bh[4], bl[4];
#pragma unroll
                for (int j = 0; j < 4; j++) {
                    int n0 = kc * BLD2 + wc * 64 + j * 16;
                    wmma::load_matrix_sync(bh[j], sBh + n0, BLD2);
                    wmma::load_matrix_sync(bl[j], sBl + n0, BLD2);
                }
                // term-outer: 8 independent acc tiles between reuses
#pragma unroll
                for (int i = 0; i < 2; i++)
#pragma unroll
                    for (int j = 0; j < 4; j++)
                        wmma::mma_sync(acc[i][j], ah[i], bh[j], acc[i][j]);
#pragma unroll
                for (int i = 0; i < 2; i++)
#pragma unroll
                    for (int j = 0; j < 4; j++)
                        wmma::mma_sync(acc[i][j], ah[i], bl[j], acc[i][j]);
#pragma unroll
                for (int i = 0; i < 2; i++)
#pragma unroll
                    for (int j = 0; j < 4; j++)
                        wmma::mma_sync(acc[i][j], al[i], bh[j], acc[i][j]);
            } else {
                wmma::fragment<wmma::matrix_b, 16, 16, 16, bf16, wmma::col_major> bh[4], bl[4];
#pragma unroll
                for (int j = 0; j < 4; j++) {
                    int n0 = (wc * 64 + j * 16) * ALD2 + kc;
                    wmma::load_matrix_sync(bh[j], sBh + n0, ALD2);
                    wmma::load_matrix_sync(bl[j], sBl + n0, ALD2);
                }
#pragma unroll
                for (int i = 0; i < 2; i++)
#pragma unroll
                    for (int j = 0; j < 4; j++)
                        wmma::mma_sync(acc[i][j], ah[i], bh[j], acc[i][j]);
#pragma unroll
                for (int i = 0; i < 2; i++)
#pragma unroll
                    for (int j = 0; j < 4; j++)
                        wmma::mma_sync(acc[i][j], ah[i], bl[j], acc[i][j]);
#pragma unroll
                for (int i = 0; i < 2; i++)
#pragma unroll
                    for (int j = 0; j < 4; j++)
                        wmma::mma_sync(acc[i][j], al[i], bh[j], acc[i][j]);
            }
        }

        if (it + 2 < nIter) ldg(it + 2, (it + 2) % 3);
        cp_commit();   // uniform group count (empty groups complete immediately)
    }

    if (!OUTSPLIT) {
#pragma unroll
        for (int i = 0; i < 2; i++) {
            int m0 = by * 128 + wr * 32 + i * 16;
#pragma unroll
            for (int j = 0; j < 4; j++) {
                int n0 = bx * 128 + wc * 64 + j * 16;
                if (n0 < N)
                    wmma::store_matrix_sync(C + (size_t)m0 * ldc + n0, acc[i][j], ldc,
                                            wmma::mem_row_major);
            }
        }
    } else {
        float* sC = reinterpret_cast<float*>(dsm);
        __syncthreads();   // all warps done reading stage buffers
#pragma unroll
        for (int i = 0; i < 2; i++)
#pragma unroll
            for (int j = 0; j < 4; j++)
                wmma::store_matrix_sync(&sC[(wr * 32 + i * 16) * 128 + wc * 64 + j * 16],
                                        acc[i][j], 128, wmma::mem_row_major);
        __syncthreads();
        int row = tid >> 1;
        int colbase = (tid & 1) << 6;
        size_t rbase = (size_t)(by * 128 + row) * ldc;
#pragma unroll
        for (int v = 0; v < 16; v++) {
            int cc = colbase + v * 4;
            int gn = bx * 128 + cc;
            if (gn < N) {
                float4 f = *reinterpret_cast<const float4*>(&sC[row * 128 + cc]);
                bf16 h[4], l[4];
                bsplit(f.x, h[0], l[0]); bsplit(f.y, h[1], l[1]);
                bsplit(f.z, h[2], l[2]); bsplit(f.w, h[3], l[3]);
                *reinterpret_cast<uint2*>(Ch + rbase + gn) = *reinterpret_cast<uint2*>(h);
                *reinterpret_cast<uint2*>(Cl + rbase + gn) = *reinterpret_cast<uint2*>(l);
            }
        }
    }
}

// ---------------- fp32 -> hi/lo split (vectorized) ----------------
__global__ __launch_bounds__(256) void split4_k(
    const float* __restrict__ in, bf16* __restrict__ h, bf16* __restrict__ l, int n4)
{
    int i = blockIdx.x * 256 + threadIdx.x;
    if (i < n4) {
        float4 f = reinterpret_cast<const float4*>(in)[i];
        bf16 hh[4], ll[4];
        bsplit(f.x, hh[0], ll[0]); bsplit(f.y, hh[1], ll[1]);
        bsplit(f.z, hh[2], ll[2]); bsplit(f.w, hh[3], ll[3]);
        reinterpret_cast<uint2*>(h)[i] = *reinterpret_cast<uint2*>(hh);
        reinterpret_cast<uint2*>(l)[i] = *reinterpret_cast<uint2*>(ll);
    }
}

// ---------------- rmsnorm: fp32 in -> hi/lo bf16 out ----------------
__global__ __launch_bounds__(256) void rmsnorm_k(
    const float* __restrict__ in, const float* __restrict__ w,
    bf16* __restrict__ oh, bf16* __restrict__ ol,
    int ncols, int ldin, int ldout)
{
    int row = blockIdx.x;
    const float* ip = in + (size_t)row * ldin;
    float ss = 0.f;
    for (int c = threadIdx.x; c < ncols; c += blockDim.x) {
        float v = ip[c];
        ss += v * v;
    }
    __shared__ float sred[32];
#pragma unroll
    for (int o = 16; o > 0; o >>= 1) ss += __shfl_xor_sync(0xffffffffu, ss, o);
    int lane = threadIdx.x & 31, wid = threadIdx.x >> 5;
    if (lane == 0) sred[wid] = ss;
    __syncthreads();
    if (wid == 0) {
        float v = (lane < 8) ? sred[lane] : 0.f;
#pragma unroll
        for (int o = 4; o > 0; o >>= 1) v += __shfl_xor_sync(0xffffffffu, v, o);
        if (lane == 0) sred[0] = v;
    }
    __syncthreads();
    float r = rsqrtf(sred[0] / (float)ncols + 1e-6f);
    size_t ob = (size_t)row * ldout;
    for (int c = threadIdx.x; c < ncols; c += blockDim.x) {
        bf16 h, l; bsplit(ip[c] * r * w[c], h, l);
        oh[ob + c] = h; ol[ob + c] = l;
    }
}

// ---------------- RoPE ----------------
__device__ __forceinline__ float2 rope_cs(int pos, int i) {
    float freq = powf(10000.0f, -(float)(2 * i) / 64.0f);
    float ang = (float)pos * freq;
    float c, s;
    sincosf(ang, &s, &c);
    return make_float2(c, s);
}

__global__ void rope_k_kernel(const float* __restrict__ ckv_kpe,
                              bf16* __restrict__ kh, bf16* __restrict__ kl) {
    int s = blockIdx.x, j = threadIdx.x;  // 64 threads
    const float* src = ckv_kpe + (size_t)s * 576 + 512;
    float2 cs = rope_cs(s, j & 31);
    float x = src[j];
    float rot = (j < 32) ? -src[j + 32] : src[j - 32];
    bf16 h, l; bsplit(x * cs.x + rot * cs.y, h, l);
    size_t o = (size_t)s * 576 + 512 + j;
    kh[o] = h; kl[o] = l;
}

__global__ void rope_q_kernel(const bf16* __restrict__ qh_in, const bf16* __restrict__ ql_in,
                              bf16* __restrict__ qh, bf16* __restrict__ ql) {
    int s = blockIdx.x, h = blockIdx.y, j = threadIdx.x;  // 64 threads
    size_t base = (size_t)s * 3072 + h * 192 + 128;
    float2 cs = rope_cs(s, j & 31);
    float x = __bfloat162float(qh_in[base + j]) + __bfloat162float(ql_in[base + j]);
    int jr = (j < 32) ? (j + 32) : (j - 32);
    float rv = __bfloat162float(qh_in[base + jr]) + __bfloat162float(ql_in[base + jr]);
    float rot = (j < 32) ? -rv : rv;
    bf16 hh, ll; bsplit(x * cs.x + rot * cs.y, hh, ll);
    size_t o = ((size_t)h * SS + s) * 576 + 512 + j;
    qh[o] = hh; ql[o] = ll;
}

// ---------------- causal softmax: fp32 scores -> hi/lo attn ----------------
__global__ __launch_bounds__(256) void softmax_causal(
    const float* __restrict__ scores, bf16* __restrict__ ah, bf16* __restrict__ al,
    float scale)
{
    int q = blockIdx.x, h = blockIdx.y;
    const float* row = scores + ((size_t)h * SS + q) * SS;
    size_t ob = ((size_t)h * SS + q) * SS;
    int tid = threadIdx.x;
    int n = q + 1;
    int kcap = min(SS, ((q >> 7) + 1) << 7);   // gemm12 reads k < kcap

    float m = -1e30f;
    for (int k = tid; k < n; k += 256) m = fmaxf(m, row[k] * scale);
    __shared__ float sred[32];
#pragma unroll
    for (int o = 16; o > 0; o >>= 1) m = fmaxf(m, __shfl_xor_sync(0xffffffffu, m, o));
    int lane = tid & 31, wid = tid >> 5;
    if (lane == 0) sred[wid] = m;
    __syncthreads();
    if (wid == 0) {
        float v = (lane < 8) ? sred[lane] : -1e30f;
#pragma unroll
        for (int o = 4; o > 0; o >>= 1) v = fmaxf(v, __shfl_xor_sync(0xffffffffu, v, o));
        if (lane == 0) sred[0] = v;
    }
    __syncthreads();
    m = sred[0];

    float ssum = 0.f;
    for (int k = tid; k < n; k += 256) ssum += __expf(row[k] * scale - m);
#pragma unroll
    for (int o = 16; o > 0; o >>= 1) ssum += __shfl_xor_sync(0xffffffffu, ssum, o);
    if (lane == 0) sred[wid] = ssum;
    __syncthreads();
    if (wid == 0) {
        float v = (lane < 8) ? sred[lane] : 0.f;
#pragma unroll
        for (int o = 4; o > 0; o >>= 1) v += __shfl_xor_sync(0xffffffffu, v, o);
        if (lane == 0) sred[0] = v;
    }
    __syncthreads();
    float inv = 1.f / sred[0];
    for (int k = tid; k < n; k += 256) {
        bf16 hh, ll; bsplit(__expf(row[k] * scale - m) * inv, hh, ll);
        ah[ob + k] = hh; al[ob + k] = ll;
    }
    bf16 z = __float2bfloat16(0.f);
    for (int k = n + tid; k < kcap; k += 256) { ah[ob + k] = z; al[ob + k] = z; }
}

// ---------------- launch ----------------
extern "C" void kernel_launch(void* const* d_in, const int* in_sizes, int n_in,
                              void* d_out, int out_size)
{
    const float* x        = (const float*)d_in[0];
    const float* w_q_a    = (const float*)d_in[1];
    const float* q_a_ln_w = (const float*)d_in[2];
    const float* w_q_b    = (const float*)d_in[3];
    const float* w_kv_a   = (const float*)d_in[4];
    const float* kv_a_ln_w= (const float*)d_in[5];
    const float* w_kv_b   = (const float*)d_in[6];
    const float* w_o      = (const float*)d_in[7];
    float* out = (float*)d_out;

    float *p_qa, *p_ckv, *p_scores;
    cudaGetSymbolAddress((void**)&p_qa, g_qa);
    cudaGetSymbolAddress((void**)&p_ckv, g_ckv);
    cudaGetSymbolAddress((void**)&p_scores, g_scores);
    bf16 *xh, *xl, *wqah, *wqal, *qah, *qal, *wqbh, *wqbl, *qh, *ql;
    bf16 *wkvah, *wkval, *kfh, *kfl, *wkvbh, *wkvbl, *woh, *wol;
    bf16 *qfh, *qfl, *wabh, *wabl, *ath, *atl, *och, *ocl;
    cudaGetSymbolAddress((void**)&xh, g_x_h);       cudaGetSymbolAddress((void**)&xl, g_x_l);
    cudaGetSymbolAddress((void**)&wqah, g_wqa_h);   cudaGetSymbolAddress((void**)&wqal, g_wqa_l);
    cudaGetSymbolAddress((void**)&qah, g_qa_h);     cudaGetSymbolAddress((void**)&qal, g_qa_l);
    cudaGetSymbolAddress((void**)&wqbh, g_wqb_h);   cudaGetSymbolAddress((void**)&wqbl, g_wqb_l);
    cudaGetSymbolAddress((void**)&qh, g_q_h);       cudaGetSymbolAddress((void**)&ql, g_q_l);
    cudaGetSymbolAddress((void**)&wkvah, g_wkva_h); cudaGetSymbolAddress((void**)&wkval, g_wkva_l);
    cudaGetSymbolAddress((void**)&kfh, g_kfull_h);  cudaGetSymbolAddress((void**)&kfl, g_kfull_l);
    cudaGetSymbolAddress((void**)&wkvbh, g_wkvb_h); cudaGetSymbolAddress((void**)&wkvbl, g_wkvb_l);
    cudaGetSymbolAddress((void**)&woh, g_wo_h);     cudaGetSymbolAddress((void**)&wol, g_wo_l);
    cudaGetSymbolAddress((void**)&qfh, g_qfull_h);  cudaGetSymbolAddress((void**)&qfl, g_qfull_l);
    cudaGetSymbolAddress((void**)&wabh, g_woabs_h); cudaGetSymbolAddress((void**)&wabl, g_woabs_l);
    cudaGetSymbolAddress((void**)&ath, g_attn_h);   cudaGetSymbolAddress((void**)&atl, g_attn_l);
    cudaGetSymbolAddress((void**)&och, g_octx_h);   cudaGetSymbolAddress((void**)&ocl, g_octx_l);

    // per-instantiation dynamic smem (NN vs TRANSB stage geometry)
    cudaFuncSetAttribute(gemm_bs<false,false,false,false>, cudaFuncAttributeMaxDynamicSharedMemorySize, SMEM_NN);
    cudaFuncSetAttribute(gemm_bs<false,false,false,true >, cudaFuncAttributeMaxDynamicSharedMemorySize, SMEM_NN);
    cudaFuncSetAttribute(gemm_bs<false,false,true ,true >, cudaFuncAttributeMaxDynamicSharedMemorySize, SMEM_NN);
    cudaFuncSetAttribute(gemm_bs<true ,false,false,true >, cudaFuncAttributeMaxDynamicSharedMemorySize, SMEM_NT);
    cudaFuncSetAttribute(gemm_bs<true ,true ,false,false>, cudaFuncAttributeMaxDynamicSharedMemorySize, SMEM_NT);

    const float sm_scale = rsqrtf((float)(DNN + DRR));
    auto spl = [&](const float* in, bf16* h, bf16* l, int n) {
        int n4 = n >> 2;
        split4_k<<<(n4 + 255) / 256, 256>>>(in, h, l, n4);
    };

    // Launch order arranged so the 6th launch (ncu -s 5 -c 1) is a big GEMM.
    // L1) split x
    spl(x, xh, xl, SS * EE);
    // L2) split w_q_a
    spl(w_q_a, wqah, wqal, EE * QLRR);
    // L3) gemm1: qa_raw = x @ w_q_a [2048x1536, K=2048] -> fp32
    gemm_bs<false,false,false,false><<<dim3(12, 16, 1), 256, SMEM_NN>>>(
        xh, xl, wqah, wqal, p_qa, nullptr, nullptr,
        SS, QLRR, EE, EE, QLRR, QLRR, 0, 0, 0);
    // L4) rmsnorm(qa) -> hi/lo
    rmsnorm_k<<<SS, 256>>>(p_qa, q_a_ln_w, qah, qal, QLRR, QLRR, QLRR);
    // L5) split w_q_b
    spl(w_q_b, wqbh, wqbl, QLRR * 3072);
    // L6) gemm3: q = qa @ w_q_b [2048x3072, K=1536] -> hi/lo   <-- PROFILED
    gemm_bs<false,false,false,true><<<dim3(24, 16, 1), 256, SMEM_NN>>>(
        qah, qal, wqbh, wqbl, nullptr, qh, ql,
        SS, 3072, QLRR, QLRR, 3072, 3072, 0, 0, 0);
    // L7) split w_kv_a
    spl(w_kv_a, wkvah, wkval, EE * 576);
    // L8) gemm4: ckv_kpe = x @ w_kv_a [2048x576, K=2048] -> fp32
    gemm_bs<false,false,false,false><<<dim3(5, 16, 1), 256, SMEM_NN>>>(
        xh, xl, wkvah, wkval, p_ckv, nullptr, nullptr,
        SS, 576, EE, EE, 576, 576, 0, 0, 0);
    // L9) kfull[:, :512] = rmsnorm(ckv) -> hi/lo
    rmsnorm_k<<<SS, 256>>>(p_ckv, kv_a_ln_w, kfh, kfl, RR, 576, 576);
    // L10) kfull[:, 512:576] = rope(k_pe)
    rope_k_kernel<<<SS, 64>>>(p_ckv, kfh, kfl);
    // L11) split w_kv_b
    spl(w_kv_b, wkvbh, wkvbl, RR * 4096);
    // L12) qfull pe section = rope(q_pe)
    rope_q_kernel<<<dim3(SS, HH), 64>>>(qh, ql, qfh, qfl);
    // L13) gemm8: qfull nope = q_nope @ w_uk^T (batched NT; M=2048 N=512 K=128)
    gemm_bs<true,false,false,true><<<dim3(4, 16, HH), 256, SMEM_NT>>>(
        qh, ql, wkvbh, wkvbl, nullptr, qfh, qfl,
        SS, RR, DNN, 3072, 4096, 576, 192LL, 256LL, (long long)SS * 576);
    // L14) split w_o
    spl(w_o, woh, wol, 2048 * 2048);
    // L15) gemm9: w_o_abs[h] = w_uv[h]^T @ w_o[h] (batched NN; M=512 N=2048 K=128)
    gemm_bs<false,false,false,true><<<dim3(16, 4, HH), 256, SMEM_NN>>>(
        wkvbh + 128, wkvbl + 128, woh, wol, nullptr, wabh, wabl,
        RR, EE, DNN, 4096, EE, EE, 256LL, (long long)DNN * EE, (long long)RR * EE);
    // L16) gemm10: scores[h] = qfull[h] @ kfull^T (batched NT, causal-skip) -> fp32
    gemm_bs<true,true,false,false><<<dim3(16, 16, HH), 256, SMEM_NT>>>(
        qfh, qfl, kfh, kfl, p_scores, nullptr, nullptr,
        SS, SS, 576, 576, 576, SS, (long long)SS * 576, 0LL, (long long)SS * SS);
    // L17) softmax -> attn hi/lo (+ zero tail to tile boundary)
    softmax_causal<<<dim3(SS, HH), 256>>>(p_scores, ath, atl, sm_scale);
    // L18) gemm12: octx = attn[h] @ ckv (batched NN, causal K-limit) -> hi/lo
    gemm_bs<false,false,true,true><<<dim3(4, 16, HH), 256, SMEM_NN>>>(
        ath, atl, kfh, kfl, nullptr, och, ocl,
        SS, RR, SS, SS, 576, HH * RR, (long long)SS * SS, 0LL, (long long)RR);
    // L19) gemm13: y = octx @ w_o_abs (NN; M=2048 N=2048 K=8192) -> fp32
    gemm_bs<false,false,false,false><<<dim3(16, 16, 1), 256, SMEM_NN>>>(
        och, ocl, wabh, wabl, out, nullptr, nullptr,
        SS, EE, HH * RR, HH * RR, EE, EE, 0, 0, 0);
}

// round 17
// speedup vs baseline: 4.2325x; 1.8305x over previous
#include <cuda_runtime.h>
#include <cuda_bf16.h>
#include <mma.h>
#include <math.h>

using namespace nvcuda;
typedef __nv_bfloat16 bf16;

#define SS 2048
#define EE 2048
#define HH 16
#define DNN 128
#define DRR 64
#define RR 512
#define QLRR 1536

// ---------------- fp32 scratch ----------------
__device__ float g_qa[SS * QLRR];
__device__ float g_ckv[SS * (RR + DRR)];                 // ckv_kpe raw [2048][576]
__device__ float g_scores[(size_t)HH * SS * SS];

// ---------------- bf16 hi/lo planes ----------------
__device__ bf16 g_x_h[SS * EE],          g_x_l[SS * EE];
__device__ bf16 g_wqa_h[EE * QLRR],      g_wqa_l[EE * QLRR];
__device__ bf16 g_qa_h[SS * QLRR],       g_qa_l[SS * QLRR];
__device__ bf16 g_wqb_h[QLRR * 3072],    g_wqb_l[QLRR * 3072];
__device__ bf16 g_q_h[SS * 3072],        g_q_l[SS * 3072];   // [s][h*192+{nope|pe}], pe roped in place
__device__ bf16 g_wkva_h[EE * 576],      g_wkva_l[EE * 576];
__device__ bf16 g_ckvp_h[SS * RR],       g_ckvp_l[SS * RR];  // rmsnormed ckv [2048][512]
__device__ bf16 g_wkvb_h[RR * 4096],     g_wkvb_l[RR * 4096];
__device__ bf16 g_wo_h[2048 * 2048],     g_wo_l[2048 * 2048];
__device__ bf16 g_kab_h[HH * SS * 192],  g_kab_l[HH * SS * 192];  // [h][n][{k_abs|k_pe}]
__device__ bf16 g_vab_h[HH * SS * DNN],  g_vab_l[HH * SS * DNN];  // [h][n][128]
__device__ bf16 g_attn_h[(size_t)HH * SS * SS], g_attn_l[(size_t)HH * SS * SS];
__device__ bf16 g_o_h[SS * 2048],        g_o_l[SS * 2048];        // [s][h*128+d]

__device__ __forceinline__ void bsplit(float v, bf16& h, bf16& l) {
    h = __float2bfloat16(v);
    l = __float2bfloat16(v - __bfloat162float(h));
}

// ---------------- cp.async helpers ----------------
__device__ __forceinline__ void cpa16(void* sdst, const void* gsrc, bool pred) {
    unsigned s = (unsigned)__cvta_generic_to_shared(sdst);
    int sz = pred ? 16 : 0;
    asm volatile("cp.async.cg.shared.global [%0], [%1], 16, %2;\n"
                 :: "r"(s), "l"(gsrc), "r"(sz));
}
__device__ __forceinline__ void cp_commit() { asm volatile("cp.async.commit_group;\n"); }
__device__ __forceinline__ void cp_wait1()  { asm volatile("cp.async.wait_group 1;\n" ::: "memory"); }

// ---------------- bf16-split GEMM, 3-stage cp.async pipeline (unchanged engine) ----------------
#define ALD2 40       // A / NT-B smem k-stride (elems)
#define BLD2 136      // NN-B smem n-stride (elems)
#define PLANE_A 5120  // 128*40
#define PLANE_BN 4352 // 32*136

#define SMEM_NN (3 * (2 * PLANE_A + 2 * PLANE_BN) * 2)  // 113664
#define SMEM_NT (3 * (4 * PLANE_A) * 2)                 // 122880

extern __shared__ bf16 dsm[];

template <bool TRANSB, bool CSKIP, bool CKLIM, bool OUTSPLIT>
__global__ __launch_bounds__(256, 2) void gemm_bs(
    const bf16* __restrict__ Ah, const bf16* __restrict__ Al,
    const bf16* __restrict__ Bh, const bf16* __restrict__ Bl,
    float* __restrict__ C, bf16* __restrict__ Ch, bf16* __restrict__ Cl,
    int M, int N, int K, int lda, int ldb, int ldc,
    long long sA, long long sB, long long sC)
{
    constexpr int PB = TRANSB ? PLANE_A : PLANE_BN;
    constexpr int STAGE_E = 2 * PLANE_A + 2 * PB;

    int bz = blockIdx.z;
    Ah += sA * bz; Al += sA * bz; Bh += sB * bz; Bl += sB * bz;
    if (OUTSPLIT) { Ch += sC * bz; Cl += sC * bz; } else { C += sC * bz; }
    int bx = blockIdx.x, by = blockIdx.y;
    if (CSKIP && bx > by) return;
    int kEnd = CKLIM ? min(K, (by + 1) * 128) : K;   // multiple of 32

    int tid = threadIdx.x;
    int wid = tid >> 5;
    int wr = wid >> 1;   // 0..3
    int wc = wid & 1;    // 0..1

    wmma::fragment<wmma::accumulator, 16, 16, 16, float> acc[2][4];
#pragma unroll
    for (int i = 0; i < 2; i++)
#pragma unroll
        for (int j = 0; j < 4; j++) wmma::fill_fragment(acc[i][j], 0.0f);

    auto ldg = [&](int it, int st) {
        int k0 = it << 5;
        bf16* base = dsm + st * STAGE_E;
        bf16* sAh = base;                 bf16* sAl = base + PLANE_A;
        bf16* sBh = base + 2 * PLANE_A;   bf16* sBl = base + 2 * PLANE_A + PB;
#pragma unroll
        for (int r = 0; r < 2; r++) {
            int c = tid * 2 + r;
            int row = c >> 2, kc = (c & 3) << 3;
            size_t go = (size_t)(by * 128 + row) * lda + k0 + kc;
            cpa16(sAh + row * ALD2 + kc, Ah + go, true);
            cpa16(sAl + row * ALD2 + kc, Al + go, true);
        }
        if (!TRANSB) {
#pragma unroll
            for (int r = 0; r < 2; r++) {
                int c = tid * 2 + r;
                int row = c >> 4, nc = (c & 15) << 3;
                int gn = bx * 128 + nc;
                bool p = gn < N;
                size_t go = p ? ((size_t)(k0 + row) * ldb + gn) : 0;
                cpa16(sBh + row * BLD2 + nc, Bh + go, p);
                cpa16(sBl + row * BLD2 + nc, Bl + go, p);
            }
        } else {
#pragma unroll
            for (int r = 0; r < 2; r++) {
                int c = tid * 2 + r;
                int row = c >> 2, kc = (c & 3) << 3;
                int gn = bx * 128 + row;
                bool p = gn < N;
                size_t go = p ? ((size_t)gn * ldb + k0 + kc) : 0;
                cpa16(sBh + row * ALD2 + kc, Bh + go, p);
                cpa16(sBl + row * ALD2 + kc, Bl + go, p);
            }
        }
    };

    int nIter = kEnd >> 5;
    ldg(0, 0); cp_commit();
    if (nIter > 1) ldg(1, 1);
    cp_commit();

    for (int it = 0; it < nIter; it++) {
        int st = it % 3;
        cp_wait1();
        __syncthreads();

        bf16* base = dsm + st * STAGE_E;
        bf16* sAh = base;                 bf16* sAl = base + PLANE_A;
        bf16* sBh = base + 2 * PLANE_A;   bf16* sBl = base + 2 * PLANE_A + PB;

#pragma unroll
        for (int kc = 0; kc < 32; kc += 16) {
            wmma::fragment<wmma::matrix_a, 16, 16, 16, bf16, wmma::row_major> ah[2], al[2];
#pragma unroll
            for (int i = 0; i < 2; i++) {
                int m0 = (wr * 32 + i * 16) * ALD2 + kc;
                wmma::load_matrix_sync(ah[i], sAh + m0, ALD2);
                wmma::load_matrix_sync(al[i], sAl + m0, ALD2);
            }
            if (!TRANSB) {
                wmma::fragment<wmma::matrix_b, 16, 16, 16, bf16, wmma::row_major> bh[4], bl[4];
#pragma unroll
                for (int j = 0; j < 4; j++) {
                    int n0 = kc * BLD2 + wc * 64 + j * 16;
                    wmma::load_matrix_sync(bh[j], sBh + n0, BLD2);
                    wmma::load_matrix_sync(bl[j], sBl + n0, BLD2);
                }
#pragma unroll
                for (int i = 0; i < 2; i++)
#pragma unroll
                    for (int j = 0; j < 4; j++)
                        wmma::mma_sync(acc[i][j], ah[i], bh[j], acc[i][j]);
#pragma unroll
                for (int i = 0; i < 2; i++)
#pragma unroll
                    for (int j = 0; j < 4; j++)
                        wmma::mma_sync(acc[i][j], ah[i], bl[j], acc[i][j]);
#pragma unroll
                for (int i = 0; i < 2; i++)
#pragma unroll
                    for (int j = 0; j < 4; j++)
                        wmma::mma_sync(acc[i][j], al[i], bh[j], acc[i][j]);
            } else {
                wmma::fragment<wmma::matrix_b, 16, 16, 16, bf16, wmma::col_major> bh[4], bl[4];
#pragma unroll
                for (int j = 0; j < 4; j++) {
                    int n0 = (wc * 64 + j * 16) * ALD2 + kc;
                    wmma::load_matrix_sync(bh[j], sBh + n0, ALD2);
                    wmma::load_matrix_sync(bl[j], sBl + n0, ALD2);
                }
#pragma unroll
                for (int i = 0; i < 2; i++)
#pragma unroll
                    for (int j = 0; j < 4; j++)
                        wmma::mma_sync(acc[i][j], ah[i], bh[j], acc[i][j]);
#pragma unroll
                for (int i = 0; i < 2; i++)
#pragma unroll
                    for (int j = 0; j < 4; j++)
                        wmma::mma_sync(acc[i][j], ah[i], bl[j], acc[i][j]);
#pragma unroll
                for (int i = 0; i < 2; i++)
#pragma unroll
                    for (int j = 0; j < 4; j++)
                        wmma::mma_sync(acc[i][j], al[i], bh[j], acc[i][j]);
            }
        }

        if (it + 2 < nIter) ldg(it + 2, (it + 2) % 3);
        cp_commit();
    }

    if (!OUTSPLIT) {
#pragma unroll
        for (int i = 0; i < 2; i++) {
            int m0 = by * 128 + wr * 32 + i * 16;
#pragma unroll
            for (int j = 0; j < 4; j++) {
                int n0 = bx * 128 + wc * 64 + j * 16;
                if (n0 < N)
                    wmma::store_matrix_sync(C + (size_t)m0 * ldc + n0, acc[i][j], ldc,
                                            wmma::mem_row_major);
            }
        }
    } else {
        float* sC = reinterpret_cast<float*>(dsm);
        __syncthreads();
#pragma unroll
        for (int i = 0; i < 2; i++)
#pragma unroll
            for (int j = 0; j < 4; j++)
                wmma::store_matrix_sync(&sC[(wr * 32 + i * 16) * 128 + wc * 64 + j * 16],
                                        acc[i][j], 128, wmma::mem_row_major);
        __syncthreads();
        int row = tid >> 1;
        int colbase = (tid & 1) << 6;
        size_t rbase = (size_t)(by * 128 + row) * ldc;
#pragma unroll
        for (int v = 0; v < 16; v++) {
            int cc = colbase + v * 4;
            int gn = bx * 128 + cc;
            if (gn < N) {
                float4 f = *reinterpret_cast<const float4*>(&sC[row * 128 + cc]);
                bf16 h[4], l[4];
                bsplit(f.x, h[0], l[0]); bsplit(f.y, h[1], l[1]);
                bsplit(f.z, h[2], l[2]); bsplit(f.w, h[3], l[3]);
                *reinterpret_cast<uint2*>(Ch + rbase + gn) = *reinterpret_cast<uint2*>(h);
                *reinterpret_cast<uint2*>(Cl + rbase + gn) = *reinterpret_cast<uint2*>(l);
            }
        }
    }
}

// ---------------- fp32 -> hi/lo split (vectorized) ----------------
__global__ __launch_bounds__(256) void split4_k(
    const float* __restrict__ in, bf16* __restrict__ h, bf16* __restrict__ l, int n4)
{
    int i = blockIdx.x * 256 + threadIdx.x;
    if (i < n4) {
        float4 f = reinterpret_cast<const float4*>(in)[i];
        bf16 hh[4], ll[4];
        bsplit(f.x, hh[0], ll[0]); bsplit(f.y, hh[1], ll[1]);
        bsplit(f.z, hh[2], ll[2]); bsplit(f.w, hh[3], ll[3]);
        reinterpret_cast<uint2*>(h)[i] = *reinterpret_cast<uint2*>(hh);
        reinterpret_cast<uint2*>(l)[i] = *reinterpret_cast<uint2*>(ll);
    }
}

// ---------------- rmsnorm: fp32 in -> hi/lo bf16 out ----------------
__global__ __launch_bounds__(256) void rmsnorm_k(
    const float* __restrict__ in, const float* __restrict__ w,
    bf16* __restrict__ oh, bf16* __restrict__ ol,
    int ncols, int ldin, int ldout)
{
    int row = blockIdx.x;
    const float* ip = in + (size_t)row * ldin;
    float ss = 0.f;
    for (int c = threadIdx.x; c < ncols; c += blockDim.x) {
        float v = ip[c];
        ss += v * v;
    }
    __shared__ float sred[32];
#pragma unroll
    for (int o = 16; o > 0; o >>= 1) ss += __shfl_xor_sync(0xffffffffu, ss, o);
    int lane = threadIdx.x & 31, wid = threadIdx.x >> 5;
    if (lane == 0) sred[wid] = ss;
    __syncthreads();
    if (wid == 0) {
        float v = (lane < 8) ? sred[lane] : 0.f;
#pragma unroll
        for (int o = 4; o > 0; o >>= 1) v += __shfl_xor_sync(0xffffffffu, v, o);
        if (lane == 0) sred[0] = v;
    }
    __syncthreads();
    float r = rsqrtf(sred[0] / (float)ncols + 1e-6f);
    size_t ob = (size_t)row * ldout;
    for (int c = threadIdx.x; c < ncols; c += blockDim.x) {
        bf16 h, l; bsplit(ip[c] * r * w[c], h, l);
        oh[ob + c] = h; ol[ob + c] = l;
    }
}

// ---------------- RoPE ----------------
__device__ __forceinline__ float2 rope_cs(int pos, int i) {
    float freq = powf(10000.0f, -(float)(2 * i) / 64.0f);
    float ang = (float)pos * freq;
    float c, s;
    sincosf(ang, &s, &c);
    return make_float2(c, s);
}

// k_pe: read raw ckv_kpe fp32, rope, broadcast into all heads' kab[:,128:192]
__global__ void rope_k_kernel(const float* __restrict__ ckv_kpe,
                              bf16* __restrict__ kabh, bf16* __restrict__ kabl) {
    int s = blockIdx.x, j = threadIdx.x;  // 64 threads
    const float* src = ckv_kpe + (size_t)s * 576 + 512;
    float2 cs = rope_cs(s, j & 31);
    float x = src[j];
    float rot = (j < 32) ? -src[j + 32] : src[j - 32];
    bf16 h, l; bsplit(x * cs.x + rot * cs.y, h, l);
#pragma unroll
    for (int hh = 0; hh < HH; hh++) {
        size_t o = ((size_t)hh * SS + s) * 192 + 128 + j;
        kabh[o] = h; kabl[o] = l;
    }
}

// q_pe roped IN PLACE on the q planes ([s][h*192+128..191])
__global__ void rope_q_kernel(bf16* __restrict__ qh, bf16* __restrict__ ql) {
    int s = blockIdx.x, h = blockIdx.y, j = threadIdx.x;  // 64 threads (2 warps)
    size_t base = (size_t)s * 3072 + h * 192 + 128;
    float2 cs = rope_cs(s, j & 31);
    float x = __bfloat162float(qh[base + j]) + __bfloat162float(ql[base + j]);
    int jr = (j < 32) ? (j + 32) : (j - 32);
    float rv = __bfloat162float(qh[base + jr]) + __bfloat162float(ql[base + jr]);
    float rot = (j < 32) ? -rv : rv;
    __syncthreads();   // all reads done before in-place writes (j and jr span warps)
    bf16 hh, ll; bsplit(x * cs.x + rot * cs.y, hh, ll);
    qh[base + j] = hh; ql[base + j] = ll;
}

// ---------------- causal softmax: fp32 scores -> hi/lo attn ----------------
__global__ __launch_bounds__(256) void softmax_causal(
    const float* __restrict__ scores, bf16* __restrict__ ah, bf16* __restrict__ al,
    float scale)
{
    int q = blockIdx.x, h = blockIdx.y;
    const float* row = scores + ((size_t)h * SS + q) * SS;
    size_t ob = ((size_t)h * SS + q) * SS;
    int tid = threadIdx.x;
    int n = q + 1;
    int kcap = min(SS, ((q >> 7) + 1) << 7);   // o-gemm reads k < kcap

    float m = -1e30f;
    for (int k = tid; k < n; k += 256) m = fmaxf(m, row[k] * scale);
    __shared__ float sred[32];
#pragma unroll
    for (int o = 16; o > 0; o >>= 1) m = fmaxf(m, __shfl_xor_sync(0xffffffffu, m, o));
    int lane = tid & 31, wid = tid >> 5;
    if (lane == 0) sred[wid] = m;
    __syncthreads();
    if (wid == 0) {
        float v = (lane < 8) ? sred[lane] : -1e30f;
#pragma unroll
        for (int o = 4; o > 0; o >>= 1) v = fmaxf(v, __shfl_xor_sync(0xffffffffu, v, o));
        if (lane == 0) sred[0] = v;
    }
    __syncthreads();
    m = sred[0];

    float ssum = 0.f;
    for (int k = tid; k < n; k += 256) ssum += __expf(row[k] * scale - m);
#pragma unroll
    for (int o = 16; o > 0; o >>= 1) ssum += __shfl_xor_sync(0xffffffffu, ssum, o);
    if (lane == 0) sred[wid] = ssum;
    __syncthreads();
    if (wid == 0) {
        float v = (lane < 8) ? sred[lane] : 0.f;
#pragma unroll
        for (int o = 4; o > 0; o >>= 1) v += __shfl_xor_sync(0xffffffffu, v, o);
        if (lane == 0) sred[0] = v;
    }
    __syncthreads();
    float inv = 1.f / sred[0];
    for (int k = tid; k < n; k += 256) {
        bf16 hh, ll; bsplit(__expf(row[k] * scale - m) * inv, hh, ll);
        ah[ob + k] = hh; al[ob + k] = ll;
    }
    bf16 z = __float2bfloat16(0.f);
    for (int k = n + tid; k < kcap; k += 256) { ah[ob + k] = z; al[ob + k] = z; }
}

// ---------------- launch ----------------
extern "C" void kernel_launch(void* const* d_in, const int* in_sizes, int n_in,
                              void* d_out, int out_size)
{
    const float* x        = (const float*)d_in[0];
    const float* w_q_a    = (const float*)d_in[1];
    const float* q_a_ln_w = (const float*)d_in[2];
    const float* w_q_b    = (const float*)d_in[3];
    const float* w_kv_a   = (const float*)d_in[4];
    const float* kv_a_ln_w= (const float*)d_in[5];
    const float* w_kv_b   = (const float*)d_in[6];
    const float* w_o      = (const float*)d_in[7];
    float* out = (float*)d_out;

    float *p_qa, *p_ckv, *p_scores;
    cudaGetSymbolAddress((void**)&p_qa, g_qa);
    cudaGetSymbolAddress((void**)&p_ckv, g_ckv);
    cudaGetSymbolAddress((void**)&p_scores, g_scores);
    bf16 *xh, *xl, *wqah, *wqal, *qah, *qal, *wqbh, *wqbl, *qh, *ql;
    bf16 *wkvah, *wkval, *ckph, *ckpl, *wkvbh, *wkvbl, *woh, *wol;
    bf16 *kabh, *kabl, *vabh, *vabl, *ath, *atl, *oh, *ol;
    cudaGetSymbolAddress((void**)&xh, g_x_h);       cudaGetSymbolAddress((void**)&xl, g_x_l);
    cudaGetSymbolAddress((void**)&wqah, g_wqa_h);   cudaGetSymbolAddress((void**)&wqal, g_wqa_l);
    cudaGetSymbolAddress((void**)&qah, g_qa_h);     cudaGetSymbolAddress((void**)&qal, g_qa_l);
    cudaGetSymbolAddress((void**)&wqbh, g_wqb_h);   cudaGetSymbolAddress((void**)&wqbl, g_wqb_l);
    cudaGetSymbolAddress((void**)&qh, g_q_h);       cudaGetSymbolAddress((void**)&ql, g_q_l);
    cudaGetSymbolAddress((void**)&wkvah, g_wkva_h); cudaGetSymbolAddress((void**)&wkval, g_wkva_l);
    cudaGetSymbolAddress((void**)&ckph, g_ckvp_h);  cudaGetSymbolAddress((void**)&ckpl, g_ckvp_l);
    cudaGetSymbolAddress((void**)&wkvbh, g_wkvb_h); cudaGetSymbolAddress((void**)&wkvbl, g_wkvb_l);
    cudaGetSymbolAddress((void**)&woh, g_wo_h);     cudaGetSymbolAddress((void**)&wol, g_wo_l);
    cudaGetSymbolAddress((void**)&kabh, g_kab_h);   cudaGetSymbolAddress((void**)&kabl, g_kab_l);
    cudaGetSymbolAddress((void**)&vabh, g_vab_h);   cudaGetSymbolAddress((void**)&vabl, g_vab_l);
    cudaGetSymbolAddress((void**)&ath, g_attn_h);   cudaGetSymbolAddress((void**)&atl, g_attn_l);
    cudaGetSymbolAddress((void**)&oh, g_o_h);       cudaGetSymbolAddress((void**)&ol, g_o_l);

    cudaFuncSetAttribute(gemm_bs<false,false,false,false>, cudaFuncAttributeMaxDynamicSharedMemorySize, SMEM_NN);
    cudaFuncSetAttribute(gemm_bs<false,false,false,true >, cudaFuncAttributeMaxDynamicSharedMemorySize, SMEM_NN);
    cudaFuncSetAttribute(gemm_bs<false,false,true ,true >, cudaFuncAttributeMaxDynamicSharedMemorySize, SMEM_NN);
    cudaFuncSetAttribute(gemm_bs<true ,true ,false,false>, cudaFuncAttributeMaxDynamicSharedMemorySize, SMEM_NT);

    const float sm_scale = rsqrtf((float)(DNN + DRR));
    auto spl = [&](const float* in, bf16* h, bf16* l, int n) {
        int n4 = n >> 2;
        split4_k<<<(n4 + 255) / 256, 256>>>(in, h, l, n4);
    };

    // --- prep splits ---
    spl(x, xh, xl, SS * EE);
    spl(w_q_a, wqah, wqal, EE * QLRR);
    spl(w_q_b, wqbh, wqbl, QLRR * 3072);
    spl(w_kv_a, wkvah, wkval, EE * 576);
    spl(w_kv_b, wkvbh, wkvbl, RR * 4096);
    spl(w_o, woh, wol, 2048 * 2048);

    // 1) qa_raw = x @ w_q_a   [2048x1536, K=2048] -> fp32
    gemm_bs<false,false,false,false><<<dim3(12, 16, 1), 256, SMEM_NN>>>(
        xh, xl, wqah, wqal, p_qa, nullptr, nullptr,
        SS, QLRR, EE, EE, QLRR, QLRR, 0, 0, 0);
    // 2) rmsnorm(qa) -> hi/lo
    rmsnorm_k<<<SS, 256>>>(p_qa, q_a_ln_w, qah, qal, QLRR, QLRR, QLRR);
    // 3) q = qa @ w_q_b [2048x3072, K=1536] -> hi/lo planes
    gemm_bs<false,false,false,true><<<dim3(24, 16, 1), 256, SMEM_NN>>>(
        qah, qal, wqbh, wqbl, nullptr, qh, ql,
        SS, 3072, QLRR, QLRR, 3072, 3072, 0, 0, 0);
    // 4) rope q_pe in place on q planes
    rope_q_kernel<<<dim3(SS, HH), 64>>>(qh, ql);
    // 5) ckv_kpe = x @ w_kv_a [2048x576, K=2048] -> fp32
    gemm_bs<false,false,false,false><<<dim3(5, 16, 1), 256, SMEM_NN>>>(
        xh, xl, wkvah, wkval, p_ckv, nullptr, nullptr,
        SS, 576, EE, EE, 576, 576, 0, 0, 0);
    // 6) ckv_norm = rmsnorm(ckv) -> hi/lo [2048][512]
    rmsnorm_k<<<SS, 256>>>(p_ckv, kv_a_ln_w, ckph, ckpl, RR, 576, RR);
    // 7) k_abs[h] = ckv_norm @ w_uk[h]  (batched NN; M=2048 N=128 K=512) -> kab[:, :128]
    gemm_bs<false,false,false,true><<<dim3(1, 16, HH), 256, SMEM_NN>>>(
        ckph, ckpl, wkvbh, wkvbl, nullptr, kabh, kabl,
        SS, DNN, RR, RR, 4096, 192, 0LL, 256LL, (long long)SS * 192);
    // 8) k_pe -> kab[:, 128:192] (all heads)
    rope_k_kernel<<<SS, 64>>>(p_ckv, kabh, kabl);
    // 9) v[h] = ckv_norm @ w_uv[h]  (batched NN; M=2048 N=128 K=512)
    gemm_bs<false,false,false,true><<<dim3(1, 16, HH), 256, SMEM_NN>>>(
        ckph, ckpl, wkvbh + 128, wkvbl + 128, nullptr, vabh, vabl,
        SS, DNN, RR, RR, 4096, DNN, 0LL, 256LL, (long long)SS * DNN);
    // 10) scores[h] = q[h] @ kab[h]^T  (batched NT, causal-skip; M=N=2048 K=192) -> fp32
    gemm_bs<true,true,false,false><<<dim3(16, 16, HH), 256, SMEM_NT>>>(
        qh, ql, kabh, kabl, p_scores, nullptr, nullptr,
        SS, SS, 192, 3072, 192, SS, 192LL, (long long)SS * 192, (long long)SS * SS);
    // 11) softmax -> attn hi/lo (+ zero tail to tile boundary)
    softmax_causal<<<dim3(SS, HH), 256>>>(p_scores, ath, atl, sm_scale);
    // 12) o[:, h*128:] = attn[h] @ v[h]  (batched NN, causal K-limit; M=2048 N=128 K=2048)
    gemm_bs<false,false,true,true><<<dim3(1, 16, HH), 256, SMEM_NN>>>(
        ath, atl, vabh, vabl, nullptr, oh, ol,
        SS, DNN, SS, SS, DNN, 2048, (long long)SS * SS, (long long)SS * DNN, 128LL);
    // 13) y = o @ w_o  (NN; M=2048 N=2048 K=2048) -> fp32
    gemm_bs<false,false,false,false><<<dim3(16, 16, 1), 256, SMEM_NN>>>(
        oh, ol, woh, wol, out, nullptr, nullptr,
        SS, EE, 2048, 2048, EE, EE, 0, 0, 0);
}